// round 1
// baseline (speedup 1.0000x reference)
#include <cuda_runtime.h>
#include <math.h>

#define TOKENS 8192
#define HID    1024
#define FFN    4096

// ---------------- scratch (allocation-free: __device__ globals) ----------------
__device__ float g_xnorm[TOKENS * HID];   // 32 MB
__device__ float g_h    [TOKENS * FFN];   // 128 MB
__device__ float g_base [TOKENS * HID];   // 32 MB
__device__ float g_t    [TOKENS * 512];   // 16 MB (adapter hidden, reused)
__device__ float g_ad0  [TOKENS * HID];   // 32 MB
__device__ float g_ad1  [TOKENS * HID];   // 32 MB

__device__ __forceinline__ float gelu_exact(float x) {
    return 0.5f * x * (1.0f + erff(x * 0.7071067811865475f));
}

// ---------------- block reduction (sum, sumsq) over 256 threads ----------------
__device__ __forceinline__ void block_reduce_sum2(float& s, float& ss) {
    #pragma unroll
    for (int off = 16; off > 0; off >>= 1) {
        s  += __shfl_down_sync(0xffffffffu, s, off);
        ss += __shfl_down_sync(0xffffffffu, ss, off);
    }
    __shared__ float sh_s[8], sh_ss[8];
    int warp = threadIdx.x >> 5, lane = threadIdx.x & 31;
    if (lane == 0) { sh_s[warp] = s; sh_ss[warp] = ss; }
    __syncthreads();
    if (warp == 0) {
        s  = (lane < 8) ? sh_s[lane]  : 0.0f;
        ss = (lane < 8) ? sh_ss[lane] : 0.0f;
        #pragma unroll
        for (int off = 4; off > 0; off >>= 1) {
            s  += __shfl_down_sync(0xffffffffu, s, off);
            ss += __shfl_down_sync(0xffffffffu, ss, off);
        }
        if (lane == 0) { sh_s[0] = s; sh_ss[0] = ss; }
    }
    __syncthreads();
    s = sh_s[0]; ss = sh_ss[0];
}

// ---------------- LayerNorm over last dim L (one row per block) ----------------
template <int L>
__global__ void __launch_bounds__(256) ln_kernel(
    const float* __restrict__ in, const float* __restrict__ gw,
    const float* __restrict__ bw, float* __restrict__ out)
{
    constexpr int PER = L / 1024;  // float4 per thread (256 threads * 4 floats)
    const size_t row = blockIdx.x;
    const float4* inr = reinterpret_cast<const float4*>(in) + row * (L / 4);

    float4 v[PER];
    float s = 0.0f, ss = 0.0f;
    #pragma unroll
    for (int i = 0; i < PER; ++i) {
        v[i] = inr[threadIdx.x + i * 256];
        s  += v[i].x + v[i].y + v[i].z + v[i].w;
        ss += v[i].x * v[i].x + v[i].y * v[i].y + v[i].z * v[i].z + v[i].w * v[i].w;
    }
    block_reduce_sum2(s, ss);
    const float mu  = s * (1.0f / L);
    const float var = ss * (1.0f / L) - mu * mu;
    const float inv = rsqrtf(var + 1e-5f);

    float4* outr = reinterpret_cast<float4*>(out) + row * (L / 4);
    const float4* g4 = reinterpret_cast<const float4*>(gw);
    const float4* b4 = reinterpret_cast<const float4*>(bw);
    #pragma unroll
    for (int i = 0; i < PER; ++i) {
        const int c = threadIdx.x + i * 256;
        const float4 gv = g4[c], bv = b4[c], x = v[i];
        float4 o;
        o.x = (x.x - mu) * inv * gv.x + bv.x;
        o.y = (x.y - mu) * inv * gv.y + bv.y;
        o.z = (x.z - mu) * inv * gv.z + bv.z;
        o.w = (x.w - mu) * inv * gv.w + bv.w;
        outr[c] = o;
    }
}

// ---------------- fp32 tiled GEMM: C = [gelu](A @ B + bias) ----------------
// A: MxK row-major, B: KxN row-major, C: MxN row-major.
// 128x128 block tile, BK=8, 256 threads, 8x8 per thread.
// Requires: M%128==0, N%128==0, K%8==0 (holds for all shapes here).
__global__ void __launch_bounds__(256, 2) gemm128(
    const float* __restrict__ A, const float* __restrict__ B,
    const float* __restrict__ bias, float* __restrict__ C,
    int M, int N, int K, int do_gelu)
{
    __shared__ float As[8][128];
    __shared__ float Bs[8][128];

    const int tid = threadIdx.x;
    const int bm  = blockIdx.y;
    const int bn  = blockIdx.x;
    const int tx  = tid & 15;   // 0..15  -> N direction
    const int ty  = tid >> 4;   // 0..15  -> M direction

    const float* Ablk = A + (size_t)bm * 128 * K;
    const float* Bblk = B + (size_t)bn * 128;

    const int arow = tid >> 1;          // 0..127
    const int acol = (tid & 1) * 4;     // 0 or 4
    const int brow = tid >> 5;          // 0..7
    const int bcol = (tid & 31) * 4;    // 0..124

    float acc[8][8];
    #pragma unroll
    for (int i = 0; i < 8; ++i)
        #pragma unroll
        for (int j = 0; j < 8; ++j) acc[i][j] = 0.0f;

    for (int kt = 0; kt < K; kt += 8) {
        const float4 av = *reinterpret_cast<const float4*>(
            Ablk + (size_t)arow * K + kt + acol);
        const float4 bv = *reinterpret_cast<const float4*>(
            Bblk + (size_t)(kt + brow) * N + bcol);

        __syncthreads();   // previous tile fully consumed
        As[acol + 0][arow] = av.x;
        As[acol + 1][arow] = av.y;
        As[acol + 2][arow] = av.z;
        As[acol + 3][arow] = av.w;
        *reinterpret_cast<float4*>(&Bs[brow][bcol]) = bv;
        __syncthreads();   // tile ready

        #pragma unroll
        for (int k = 0; k < 8; ++k) {
            float a[8], b[8];
            *reinterpret_cast<float4*>(a)     = *reinterpret_cast<const float4*>(&As[k][ty * 8]);
            *reinterpret_cast<float4*>(a + 4) = *reinterpret_cast<const float4*>(&As[k][ty * 8 + 4]);
            *reinterpret_cast<float4*>(b)     = *reinterpret_cast<const float4*>(&Bs[k][tx * 8]);
            *reinterpret_cast<float4*>(b + 4) = *reinterpret_cast<const float4*>(&Bs[k][tx * 8 + 4]);
            #pragma unroll
            for (int i = 0; i < 8; ++i)
                #pragma unroll
                for (int j = 0; j < 8; ++j)
                    acc[i][j] = fmaf(a[i], b[j], acc[i][j]);
        }
    }

    // epilogue: bias (+ optional exact GELU), vectorized stores
    const int crow0 = bm * 128 + ty * 8;
    const int ccol0 = bn * 128 + tx * 8;
    float bsv[8];
    #pragma unroll
    for (int j = 0; j < 8; ++j) bsv[j] = bias[ccol0 + j];

    #pragma unroll
    for (int i = 0; i < 8; ++i) {
        float r[8];
        #pragma unroll
        for (int j = 0; j < 8; ++j) {
            float c = acc[i][j] + bsv[j];
            if (do_gelu) c = gelu_exact(c);
            r[j] = c;
        }
        float* crow = C + (size_t)(crow0 + i) * N + ccol0;
        *reinterpret_cast<float4*>(crow)     = make_float4(r[0], r[1], r[2], r[3]);
        *reinterpret_cast<float4*>(crow + 4) = make_float4(r[4], r[5], r[6], r[7]);
    }
}

// ---------------- routed combine ----------------
__global__ void __launch_bounds__(256) combine_kernel(
    const float* __restrict__ base, const float* __restrict__ ad0,
    const float* __restrict__ ad1,  const float* __restrict__ xn,
    const float* __restrict__ wm,   const int* __restrict__ idx,
    float* __restrict__ out)
{
    const int t = blockIdx.x;
    const float w  = wm[t];
    const float w1 = 1.0f - w;
    const int id = idx[t];
    const float* asel = (id == 0) ? ad0 : ((id == 1) ? ad1 : xn);
    const float4* a4 = reinterpret_cast<const float4*>(asel);
    const float4* b4 = reinterpret_cast<const float4*>(base);
    float4* o4 = reinterpret_cast<float4*>(out);

    const int off = t * (HID / 4) + threadIdx.x;
    const float4 b = b4[off];
    const float4 a = a4[off];
    float4 o;
    o.x = b.x * w + a.x * w1;
    o.y = b.y * w + a.y * w1;
    o.z = b.z * w + a.z * w1;
    o.w = b.w * w + a.w * w1;
    o4[off] = o;
}

// ---------------- launch ----------------
extern "C" void kernel_launch(void* const* d_in, const int* in_sizes, int n_in,
                              void* d_out, int out_size)
{
    const float* x        = (const float*)d_in[0];
    const float* wm       = (const float*)d_in[1];
    const int*   widx     = (const int*)  d_in[2];
    const float* ln_in_g  = (const float*)d_in[3];
    const float* ln_in_b  = (const float*)d_in[4];
    const float* W1       = (const float*)d_in[5];
    const float* b1       = (const float*)d_in[6];
    const float* ln_h_g   = (const float*)d_in[7];
    const float* ln_h_b   = (const float*)d_in[8];
    const float* W2       = (const float*)d_in[9];
    const float* b2       = (const float*)d_in[10];
    const float* a256_w1  = (const float*)d_in[11];
    const float* a256_b1  = (const float*)d_in[12];
    const float* a256_w2  = (const float*)d_in[13];
    const float* a256_b2  = (const float*)d_in[14];
    const float* a512_w1  = (const float*)d_in[15];
    const float* a512_b1  = (const float*)d_in[16];
    const float* a512_w2  = (const float*)d_in[17];
    const float* a512_b2  = (const float*)d_in[18];
    float* out = (float*)d_out;

    float *xnorm, *h, *base, *t, *ad0, *ad1;
    cudaGetSymbolAddress((void**)&xnorm, g_xnorm);
    cudaGetSymbolAddress((void**)&h,     g_h);
    cudaGetSymbolAddress((void**)&base,  g_base);
    cudaGetSymbolAddress((void**)&t,     g_t);
    cudaGetSymbolAddress((void**)&ad0,   g_ad0);
    cudaGetSymbolAddress((void**)&ad1,   g_ad1);

    // 1) x_norm = LN(x)
    ln_kernel<HID><<<TOKENS, 256>>>(x, ln_in_g, ln_in_b, xnorm);

    // 2) h = gelu(x_norm @ W1 + b1)    [8192 x 4096, K=1024]
    gemm128<<<dim3(FFN / 128, TOKENS / 128), 256>>>(xnorm, W1, b1, h,
                                                    TOKENS, FFN, HID, 1);

    // 3) h = LN(h)   (in place; row is cached in registers before writeback)
    ln_kernel<FFN><<<TOKENS, 256>>>(h, ln_h_g, ln_h_b, h);

    // 4) base = h @ W2 + b2            [8192 x 1024, K=4096]
    gemm128<<<dim3(HID / 128, TOKENS / 128), 256>>>(h, W2, b2, base,
                                                    TOKENS, HID, FFN, 0);

    // 5) adapter 256: t = gelu(x_norm @ a256_w1 + b); ad0 = t @ a256_w2 + b
    gemm128<<<dim3(256 / 128, TOKENS / 128), 256>>>(xnorm, a256_w1, a256_b1, t,
                                                    TOKENS, 256, HID, 1);
    gemm128<<<dim3(HID / 128, TOKENS / 128), 256>>>(t, a256_w2, a256_b2, ad0,
                                                    TOKENS, HID, 256, 0);

    // 6) adapter 512
    gemm128<<<dim3(512 / 128, TOKENS / 128), 256>>>(xnorm, a512_w1, a512_b1, t,
                                                    TOKENS, 512, HID, 1);
    gemm128<<<dim3(HID / 128, TOKENS / 128), 256>>>(t, a512_w2, a512_b2, ad1,
                                                    TOKENS, HID, 512, 0);

    // 7) out = base*wm + select(idx; ad0, ad1, x_norm)*(1-wm)
    combine_kernel<<<TOKENS, 256>>>(base, ad0, ad1, xnorm, wm, widx, out);
}

// round 3
// speedup vs baseline: 1.9086x; 1.9086x over previous
#include <cuda_runtime.h>
#include <cuda_bf16.h>
#include <math.h>
#include <stdint.h>

#define TOKENS 8192
#define HID    1024
#define FFN    4096

// ============================ scratch (device globals) ============================
// A-style triple layout along K: [Ah | Al | Ah]   (row stride 3K)
// B-style triple layout along K: [Bh | Bh | Bl]   (row stride 3K)
__device__ float g_xnorm[TOKENS * HID];                    // fp32 x_norm (combine needs it)
__device__ __nv_bfloat16 g_xn3[TOKENS * 3 * HID];          // A' for GEMM1/adapters
__device__ float g_h[TOKENS * FFN];                        // fp32 h (pre-LN)
__device__ __nv_bfloat16 g_hn3[TOKENS * 3 * FFN];          // A' for GEMM2
__device__ float g_base[TOKENS * HID], g_ad0[TOKENS * HID], g_ad1[TOKENS * HID];
__device__ __nv_bfloat16 g_t03[TOKENS * 3 * 256];          // adapter256 mid (A')
__device__ __nv_bfloat16 g_t13[TOKENS * 3 * 512];          // adapter512 mid (A')
__device__ __nv_bfloat16 g_w1t3[FFN * 3 * HID];            // B' W1^T  [4096 x 3*1024]
__device__ __nv_bfloat16 g_w2t3[HID * 3 * FFN];            // B' W2^T  [1024 x 3*4096]
__device__ __nv_bfloat16 g_aw1t3[256 * 3 * HID];
__device__ __nv_bfloat16 g_aw2t3[HID * 3 * 256];
__device__ __nv_bfloat16 g_bw1t3[512 * 3 * HID];
__device__ __nv_bfloat16 g_bw2t3[HID * 3 * 512];

__device__ __forceinline__ float gelu_exact(float x) {
    return 0.5f * x * (1.0f + erff(x * 0.7071067811865475f));
}

__device__ __forceinline__ uint32_t smem_u32(const void* p) {
    uint32_t a;
    asm("{ .reg .u64 t; cvta.to.shared.u64 t, %1; cvt.u32.u64 %0, t; }" : "=r"(a) : "l"(p));
    return a;
}

#define CP_ASYNC16(s, g) \
    asm volatile("cp.async.cg.shared.global [%0], [%1], 16;" :: "r"(s), "l"(g))
#define CP_COMMIT() asm volatile("cp.async.commit_group;")
#define CP_WAIT1()  asm volatile("cp.async.wait_group 1;")

#define LDSM4(r0, r1, r2, r3, addr) \
    asm volatile("ldmatrix.sync.aligned.m8n8.x4.shared.b16 {%0,%1,%2,%3}, [%4];" \
                 : "=r"(r0), "=r"(r1), "=r"(r2), "=r"(r3) : "r"(addr))

#define MMA16816(d, a0, a1, a2, a3, b0, b1) \
    asm volatile("mma.sync.aligned.m16n8k16.row.col.f32.bf16.bf16.f32 " \
                 "{%0,%1,%2,%3}, {%4,%5,%6,%7}, {%8,%9}, {%0,%1,%2,%3};" \
                 : "+f"((d)[0]), "+f"((d)[1]), "+f"((d)[2]), "+f"((d)[3]) \
                 : "r"(a0), "r"(a1), "r"(a2), "r"(a3), "r"(b0), "r"(b1))

// ============================ transpose + bf16 hi/lo split (B' layout) ============================
// W [K x N] fp32 row-major -> B' [N x 3K] bf16: hi at k, hi at K+k, lo at 2K+k
__global__ void __launch_bounds__(256) transpose_split(
    const float* __restrict__ W, int K, int N, __nv_bfloat16* __restrict__ T3)
{
    __shared__ float s[32][33];
    const int n0 = blockIdx.x * 32, k0 = blockIdx.y * 32;
    const int tr = threadIdx.x >> 3;
    const int tc = (threadIdx.x & 7) * 4;
    const float4 v = *reinterpret_cast<const float4*>(W + (size_t)(k0 + tr) * N + n0 + tc);
    s[tr][tc + 0] = v.x; s[tr][tc + 1] = v.y; s[tr][tc + 2] = v.z; s[tr][tc + 3] = v.w;
    __syncthreads();
    __nv_bfloat162 hv[2], lv[2];
    #pragma unroll
    for (int q = 0; q < 2; ++q) {
        const float x0 = s[tc + q * 2 + 0][tr];
        const float x1 = s[tc + q * 2 + 1][tr];
        __nv_bfloat16 h0 = __float2bfloat16(x0), h1 = __float2bfloat16(x1);
        hv[q] = __halves2bfloat162(h0, h1);
        lv[q] = __halves2bfloat162(__float2bfloat16(x0 - __bfloat162float(h0)),
                                   __float2bfloat16(x1 - __bfloat162float(h1)));
    }
    const size_t rb = (size_t)(n0 + tr) * (3 * K);
    const int kk = k0 + tc;
    #pragma unroll
    for (int q = 0; q < 2; ++q) {
        *reinterpret_cast<__nv_bfloat162*>(T3 + rb + kk + q * 2)         = hv[q];
        *reinterpret_cast<__nv_bfloat162*>(T3 + rb + K + kk + q * 2)     = hv[q];
        *reinterpret_cast<__nv_bfloat162*>(T3 + rb + 2 * K + kk + q * 2) = lv[q];
    }
}

// ============================ LayerNorm -> fp32 (optional) + A' triple bf16 ============================
__device__ __forceinline__ void block_reduce_sum2(float& s, float& ss) {
    #pragma unroll
    for (int off = 16; off > 0; off >>= 1) {
        s  += __shfl_down_sync(0xffffffffu, s, off);
        ss += __shfl_down_sync(0xffffffffu, ss, off);
    }
    __shared__ float sh_s[8], sh_ss[8];
    int warp = threadIdx.x >> 5, lane = threadIdx.x & 31;
    if (lane == 0) { sh_s[warp] = s; sh_ss[warp] = ss; }
    __syncthreads();
    if (warp == 0) {
        s  = (lane < 8) ? sh_s[lane]  : 0.0f;
        ss = (lane < 8) ? sh_ss[lane] : 0.0f;
        #pragma unroll
        for (int off = 4; off > 0; off >>= 1) {
            s  += __shfl_down_sync(0xffffffffu, s, off);
            ss += __shfl_down_sync(0xffffffffu, ss, off);
        }
        if (lane == 0) { sh_s[0] = s; sh_ss[0] = ss; }
    }
    __syncthreads();
    s = sh_s[0]; ss = sh_ss[0];
}

template <int L>
__global__ void __launch_bounds__(256) ln_kernel(
    const float* __restrict__ in, const float* __restrict__ gw,
    const float* __restrict__ bw, float* __restrict__ outf,
    __nv_bfloat16* __restrict__ o3)
{
    constexpr int PER = L / 1024;
    const size_t row = blockIdx.x;
    const float4* inr = reinterpret_cast<const float4*>(in) + row * (L / 4);

    float4 v[PER];
    float s = 0.0f, ss = 0.0f;
    #pragma unroll
    for (int i = 0; i < PER; ++i) {
        v[i] = inr[threadIdx.x + i * 256];
        s  += v[i].x + v[i].y + v[i].z + v[i].w;
        ss += v[i].x * v[i].x + v[i].y * v[i].y + v[i].z * v[i].z + v[i].w * v[i].w;
    }
    block_reduce_sum2(s, ss);
    const float mu  = s * (1.0f / L);
    const float var = ss * (1.0f / L) - mu * mu;
    const float inv = rsqrtf(var + 1e-5f);

    const float4* g4 = reinterpret_cast<const float4*>(gw);
    const float4* b4 = reinterpret_cast<const float4*>(bw);
    float4* outr = outf ? reinterpret_cast<float4*>(outf) + row * (L / 4) : nullptr;
    __nv_bfloat16* o3r = o3 + row * (size_t)(3 * L);

    #pragma unroll
    for (int i = 0; i < PER; ++i) {
        const int c = threadIdx.x + i * 256;
        const float4 gv = g4[c], bv = b4[c], x = v[i];
        float4 o;
        o.x = (x.x - mu) * inv * gv.x + bv.x;
        o.y = (x.y - mu) * inv * gv.y + bv.y;
        o.z = (x.z - mu) * inv * gv.z + bv.z;
        o.w = (x.w - mu) * inv * gv.w + bv.w;
        if (outr) outr[c] = o;
        __nv_bfloat16 h0 = __float2bfloat16(o.x), h1 = __float2bfloat16(o.y);
        __nv_bfloat16 h2 = __float2bfloat16(o.z), h3 = __float2bfloat16(o.w);
        __nv_bfloat162 hv0 = __halves2bfloat162(h0, h1);
        __nv_bfloat162 hv1 = __halves2bfloat162(h2, h3);
        __nv_bfloat162 lv0 = __halves2bfloat162(__float2bfloat16(o.x - __bfloat162float(h0)),
                                                __float2bfloat16(o.y - __bfloat162float(h1)));
        __nv_bfloat162 lv1 = __halves2bfloat162(__float2bfloat16(o.z - __bfloat162float(h2)),
                                                __float2bfloat16(o.w - __bfloat162float(h3)));
        const int cb = c * 4;
        // A' layout: [Ah | Al | Ah]
        *reinterpret_cast<__nv_bfloat162*>(o3r + cb)             = hv0;
        *reinterpret_cast<__nv_bfloat162*>(o3r + cb + 2)         = hv1;
        *reinterpret_cast<__nv_bfloat162*>(o3r + L + cb)         = lv0;
        *reinterpret_cast<__nv_bfloat162*>(o3r + L + cb + 2)     = lv1;
        *reinterpret_cast<__nv_bfloat162*>(o3r + 2 * L + cb)     = hv0;
        *reinterpret_cast<__nv_bfloat162*>(o3r + 2 * L + cb + 2) = hv1;
    }
}

// ============================ bf16 mma.sync GEMM ============================
// C[M,N] = act(A' @ B'^T + bias).  A': [M x Kp] bf16 row-major, B': [N x Kp] bf16 row-major.
// BM=128, BN=128, BK=64, 128 threads (4 warps, 2x2 of 64x64 warp tiles), 3-stage cp.async.
#define GSTAGES 3
#define GSTAGE_BYTES 32768            // A 16KB + B 16KB
#define GEMM_SMEM (GSTAGES * GSTAGE_BYTES)

__device__ __forceinline__ void g_load_stage(
    const __nv_bfloat16* __restrict__ Ag, const __nv_bfloat16* __restrict__ Bg,
    int Kp, int kc, uint32_t sA, uint32_t sB, int tid)
{
    #pragma unroll
    for (int p = 0; p < 8; ++p) {
        const int idx = tid + p * 128;
        const int row = idx >> 3, ch = idx & 7;
        const uint32_t so = row * 128 + ((ch ^ (row & 7)) << 4);
        CP_ASYNC16(sA + so, Ag + (size_t)row * Kp + kc + ch * 8);
    }
    #pragma unroll
    for (int p = 0; p < 8; ++p) {
        const int idx = tid + p * 128;
        const int row = idx >> 3, ch = idx & 7;
        const uint32_t so = row * 128 + ((ch ^ (row & 7)) << 4);
        CP_ASYNC16(sB + so, Bg + (size_t)row * Kp + kc + ch * 8);
    }
}

__global__ void __launch_bounds__(128, 2) gemm_bf16(
    const __nv_bfloat16* __restrict__ A3, const __nv_bfloat16* __restrict__ B3,
    const float* __restrict__ bias,
    float* __restrict__ Cf, __nv_bfloat16* __restrict__ C3,
    int M, int N, int Kp, int do_gelu)
{
    extern __shared__ char smem[];
    const uint32_t sbase = smem_u32(smem);
    const int tid = threadIdx.x, lane = tid & 31, wid = tid >> 5;
    const int warp_m = wid & 1, warp_n = wid >> 1;
    const int bm = blockIdx.y, bn = blockIdx.x;

    const __nv_bfloat16* Ag = A3 + (size_t)bm * 128 * Kp;
    const __nv_bfloat16* Bg = B3 + (size_t)bn * 128 * Kp;

    // ldmatrix per-thread address precompute
    uint32_t aBase[4], aSw[4], bBase[4], bSw[4];
    const uint32_t hiA = (lane & 16);            // 0 or 16 bytes
    const uint32_t hiB = ((lane & 8) << 1);      // 0 or 16 bytes
    #pragma unroll
    for (int mt = 0; mt < 4; ++mt) {
        const int r = warp_m * 64 + mt * 16 + (lane & 15);
        aBase[mt] = r * 128;
        aSw[mt]   = (r & 7) << 4;
    }
    #pragma unroll
    for (int ng = 0; ng < 4; ++ng) {
        const int r = warp_n * 64 + ng * 16 + (lane & 7) + ((lane & 16) >> 1);
        bBase[ng] = r * 128;
        bSw[ng]   = (r & 7) << 4;
    }

    float acc[4][8][4];
    #pragma unroll
    for (int i = 0; i < 4; ++i)
        #pragma unroll
        for (int j = 0; j < 8; ++j)
            #pragma unroll
            for (int q = 0; q < 4; ++q) acc[i][j][q] = 0.0f;

    const int ntile = Kp >> 6;

    // prologue: stages 0,1
    g_load_stage(Ag, Bg, Kp, 0, sbase, sbase + 16384, tid);
    CP_COMMIT();
    g_load_stage(Ag, Bg, Kp, 64, sbase + GSTAGE_BYTES, sbase + GSTAGE_BYTES + 16384, tid);
    CP_COMMIT();

    for (int t = 0; t < ntile; ++t) {
        CP_WAIT1();
        __syncthreads();
        if (t + 2 < ntile) {
            const int slot = (t + 2) % GSTAGES;
            g_load_stage(Ag, Bg, Kp, (t + 2) * 64,
                         sbase + slot * GSTAGE_BYTES, sbase + slot * GSTAGE_BYTES + 16384, tid);
            CP_COMMIT();
        }
        const uint32_t sA = sbase + (t % GSTAGES) * GSTAGE_BYTES;
        const uint32_t sB = sA + 16384;

        #pragma unroll
        for (int j = 0; j < 4; ++j) {
            uint32_t a[4][4], b[4][4];
            #pragma unroll
            for (int mt = 0; mt < 4; ++mt)
                LDSM4(a[mt][0], a[mt][1], a[mt][2], a[mt][3],
                      sA + aBase[mt] + (((uint32_t)(j * 32) + hiA) ^ aSw[mt]));
            #pragma unroll
            for (int ng = 0; ng < 4; ++ng)
                LDSM4(b[ng][0], b[ng][1], b[ng][2], b[ng][3],
                      sB + bBase[ng] + (((uint32_t)(j * 32) + hiB) ^ bSw[ng]));
            #pragma unroll
            for (int mt = 0; mt < 4; ++mt)
                #pragma unroll
                for (int nt = 0; nt < 8; ++nt) {
                    const int ng = nt >> 1;
                    if (nt & 1) MMA16816(acc[mt][nt], a[mt][0], a[mt][1], a[mt][2], a[mt][3],
                                         b[ng][2], b[ng][3]);
                    else        MMA16816(acc[mt][nt], a[mt][0], a[mt][1], a[mt][2], a[mt][3],
                                         b[ng][0], b[ng][1]);
                }
        }
        __syncthreads();
    }

    // ---------------- epilogue ----------------
    const int row0 = bm * 128 + warp_m * 64 + (lane >> 2);
    const int col0 = bn * 128 + warp_n * 64 + (lane & 3) * 2;

    #pragma unroll
    for (int mt = 0; mt < 4; ++mt) {
        #pragma unroll
        for (int nt = 0; nt < 8; ++nt) {
            const int gc = col0 + nt * 8;
            const float bz0 = bias[gc], bz1 = bias[gc + 1];
            float v[4];
            v[0] = acc[mt][nt][0] + bz0;
            v[1] = acc[mt][nt][1] + bz1;
            v[2] = acc[mt][nt][2] + bz0;
            v[3] = acc[mt][nt][3] + bz1;
            if (do_gelu) {
                #pragma unroll
                for (int q = 0; q < 4; ++q) v[q] = gelu_exact(v[q]);
            }
            const size_t r0 = (size_t)(row0 + mt * 16);
            const size_t r1 = r0 + 8;
            if (Cf) {
                *reinterpret_cast<float2*>(Cf + r0 * N + gc) = make_float2(v[0], v[1]);
                *reinterpret_cast<float2*>(Cf + r1 * N + gc) = make_float2(v[2], v[3]);
            }
            if (C3) {
                // A' triple layout: hi @ col, lo @ N+col, hi @ 2N+col
                #pragma unroll
                for (int rr = 0; rr < 2; ++rr) {
                    const size_t rb = (rr ? r1 : r0) * (size_t)(3 * N);
                    const float x0 = v[rr * 2], x1 = v[rr * 2 + 1];
                    __nv_bfloat16 h0 = __float2bfloat16(x0), h1 = __float2bfloat16(x1);
                    __nv_bfloat162 hv = __halves2bfloat162(h0, h1);
                    __nv_bfloat162 lv = __halves2bfloat162(
                        __float2bfloat16(x0 - __bfloat162float(h0)),
                        __float2bfloat16(x1 - __bfloat162float(h1)));
                    *reinterpret_cast<__nv_bfloat162*>(C3 + rb + gc)         = hv;
                    *reinterpret_cast<__nv_bfloat162*>(C3 + rb + N + gc)     = lv;
                    *reinterpret_cast<__nv_bfloat162*>(C3 + rb + 2 * N + gc) = hv;
                }
            }
        }
    }
}

// ============================ routed combine ============================
__global__ void __launch_bounds__(256) combine_kernel(
    const float* __restrict__ base, const float* __restrict__ ad0,
    const float* __restrict__ ad1,  const float* __restrict__ xn,
    const float* __restrict__ wm,   const int* __restrict__ idx,
    float* __restrict__ out)
{
    const int t = blockIdx.x;
    const float w  = wm[t];
    const float w1 = 1.0f - w;
    const int id = idx[t];
    const float* asel = (id == 0) ? ad0 : ((id == 1) ? ad1 : xn);
    const int off = t * (HID / 4) + threadIdx.x;
    const float4 b = reinterpret_cast<const float4*>(base)[off];
    const float4 a = reinterpret_cast<const float4*>(asel)[off];
    float4 o;
    o.x = b.x * w + a.x * w1;
    o.y = b.y * w + a.y * w1;
    o.z = b.z * w + a.z * w1;
    o.w = b.w * w + a.w * w1;
    reinterpret_cast<float4*>(out)[off] = o;
}

// ============================ launch ============================
extern "C" void kernel_launch(void* const* d_in, const int* in_sizes, int n_in,
                              void* d_out, int out_size)
{
    const float* x        = (const float*)d_in[0];
    const float* wm       = (const float*)d_in[1];
    const int*   widx     = (const int*)  d_in[2];
    const float* ln_in_g  = (const float*)d_in[3];
    const float* ln_in_b  = (const float*)d_in[4];
    const float* W1       = (const float*)d_in[5];
    const float* b1       = (const float*)d_in[6];
    const float* ln_h_g   = (const float*)d_in[7];
    const float* ln_h_b   = (const float*)d_in[8];
    const float* W2       = (const float*)d_in[9];
    const float* b2       = (const float*)d_in[10];
    const float* a256_w1  = (const float*)d_in[11];
    const float* a256_b1  = (const float*)d_in[12];
    const float* a256_w2  = (const float*)d_in[13];
    const float* a256_b2  = (const float*)d_in[14];
    const float* a512_w1  = (const float*)d_in[15];
    const float* a512_b1  = (const float*)d_in[16];
    const float* a512_w2  = (const float*)d_in[17];
    const float* a512_b2  = (const float*)d_in[18];
    float* out = (float*)d_out;

    cudaFuncSetAttribute(gemm_bf16, cudaFuncAttributeMaxDynamicSharedMemorySize, GEMM_SMEM);

    float *xnorm, *h, *base, *ad0, *ad1;
    __nv_bfloat16 *xn3, *hn3, *t03, *t13, *w1t3, *w2t3, *aw1t3, *aw2t3, *bw1t3, *bw2t3;
    cudaGetSymbolAddress((void**)&xnorm, g_xnorm);
    cudaGetSymbolAddress((void**)&h,     g_h);
    cudaGetSymbolAddress((void**)&base,  g_base);
    cudaGetSymbolAddress((void**)&ad0,   g_ad0);
    cudaGetSymbolAddress((void**)&ad1,   g_ad1);
    cudaGetSymbolAddress((void**)&xn3,   g_xn3);
    cudaGetSymbolAddress((void**)&hn3,   g_hn3);
    cudaGetSymbolAddress((void**)&t03,   g_t03);
    cudaGetSymbolAddress((void**)&t13,   g_t13);
    cudaGetSymbolAddress((void**)&w1t3,  g_w1t3);
    cudaGetSymbolAddress((void**)&w2t3,  g_w2t3);
    cudaGetSymbolAddress((void**)&aw1t3, g_aw1t3);
    cudaGetSymbolAddress((void**)&aw2t3, g_aw2t3);
    cudaGetSymbolAddress((void**)&bw1t3, g_bw1t3);
    cudaGetSymbolAddress((void**)&bw2t3, g_bw2t3);

    // --- weight transpose + split into B' triple layout ---
    transpose_split<<<dim3(FFN / 32, HID / 32), 256>>>(W1, HID, FFN, w1t3);
    transpose_split<<<dim3(HID / 32, FFN / 32), 256>>>(W2, FFN, HID, w2t3);
    transpose_split<<<dim3(256 / 32, HID / 32), 256>>>(a256_w1, HID, 256, aw1t3);
    transpose_split<<<dim3(HID / 32, 256 / 32), 256>>>(a256_w2, 256, HID, aw2t3);
    transpose_split<<<dim3(512 / 32, HID / 32), 256>>>(a512_w1, HID, 512, bw1t3);
    transpose_split<<<dim3(HID / 32, 512 / 32), 256>>>(a512_w2, 512, HID, bw2t3);

    // --- x_norm = LN(x): fp32 + A' ---
    ln_kernel<HID><<<TOKENS, 256>>>(x, ln_in_g, ln_in_b, xnorm, xn3);

    // --- h = gelu(x_norm @ W1 + b1)   [8192 x 4096, Kp=3072] ---
    gemm_bf16<<<dim3(FFN / 128, TOKENS / 128), 128, GEMM_SMEM>>>(
        xn3, w1t3, b1, h, nullptr, TOKENS, FFN, 3 * HID, 1);

    // --- h_norm = LN(h): A' only ---
    ln_kernel<FFN><<<TOKENS, 256>>>(h, ln_h_g, ln_h_b, nullptr, hn3);

    // --- base = h_norm @ W2 + b2     [8192 x 1024, Kp=12288] ---
    gemm_bf16<<<dim3(HID / 128, TOKENS / 128), 128, GEMM_SMEM>>>(
        hn3, w2t3, b2, base, nullptr, TOKENS, HID, 3 * FFN, 0);

    // --- adapter 256 ---
    gemm_bf16<<<dim3(256 / 128, TOKENS / 128), 128, GEMM_SMEM>>>(
        xn3, aw1t3, a256_b1, nullptr, t03, TOKENS, 256, 3 * HID, 1);
    gemm_bf16<<<dim3(HID / 128, TOKENS / 128), 128, GEMM_SMEM>>>(
        t03, aw2t3, a256_b2, ad0, nullptr, TOKENS, HID, 3 * 256, 0);

    // --- adapter 512 ---
    gemm_bf16<<<dim3(512 / 128, TOKENS / 128), 128, GEMM_SMEM>>>(
        xn3, bw1t3, a512_b1, nullptr, t13, TOKENS, 512, 3 * HID, 1);
    gemm_bf16<<<dim3(HID / 128, TOKENS / 128), 128, GEMM_SMEM>>>(
        t13, bw2t3, a512_b2, ad1, nullptr, TOKENS, HID, 3 * 512, 0);

    // --- routed combine ---
    combine_kernel<<<TOKENS, 256>>>(base, ad0, ad1, xnorm, wm, widx, out);
}

// round 4
// speedup vs baseline: 3.9290x; 2.0586x over previous
#include <cuda_runtime.h>
#include <cuda_fp16.h>
#include <math.h>
#include <stdint.h>

#define TOKENS 8192
#define HID    1024
#define FFN    4096

// ============================ scratch (device globals) ============================
__device__ float  g_xnorm[TOKENS * HID];          // fp32 x_norm (combine)
__device__ __half g_xnh[TOKENS * HID];            // fp16 x_norm (GEMM A)
__device__ float  g_h[TOKENS * FFN];              // fp32 h pre-LN
__device__ __half g_hnh[TOKENS * FFN];            // fp16 h_norm
__device__ float  g_base[TOKENS * HID], g_ad0[TOKENS * HID], g_ad1[TOKENS * HID];
__device__ __half g_t0h[TOKENS * 256];
__device__ __half g_t1h[TOKENS * 512];
// weight planes: W^T [N x K] fp16 hi + lo
__device__ __half g_w1t_h[FFN * HID],  g_w1t_l[FFN * HID];
__device__ __half g_w2t_h[HID * FFN],  g_w2t_l[HID * FFN];
__device__ __half g_aw1t_h[256 * HID], g_aw1t_l[256 * HID];
__device__ __half g_aw2t_h[HID * 256], g_aw2t_l[HID * 256];
__device__ __half g_bw1t_h[512 * HID], g_bw1t_l[512 * HID];
__device__ __half g_bw2t_h[HID * 512], g_bw2t_l[HID * 512];

__device__ __forceinline__ float gelu_exact(float x) {
    return 0.5f * x * (1.0f + erff(x * 0.7071067811865475f));
}
__device__ __forceinline__ uint32_t smem_u32(const void* p) {
    uint32_t a;
    asm("{ .reg .u64 t; cvta.to.shared.u64 t, %1; cvt.u32.u64 %0, t; }" : "=r"(a) : "l"(p));
    return a;
}

#define CP_ASYNC16(s, g) \
    asm volatile("cp.async.cg.shared.global [%0], [%1], 16;" :: "r"(s), "l"(g))
#define CP_COMMIT() asm volatile("cp.async.commit_group;")
#define CP_WAIT1()  asm volatile("cp.async.wait_group 1;")

#define LDSM4(r0, r1, r2, r3, addr) \
    asm volatile("ldmatrix.sync.aligned.m8n8.x4.shared.b16 {%0,%1,%2,%3}, [%4];" \
                 : "=r"(r0), "=r"(r1), "=r"(r2), "=r"(r3) : "r"(addr))

#define MMA16816F16(d, a0, a1, a2, a3, b0, b1) \
    asm volatile("mma.sync.aligned.m16n8k16.row.col.f32.f16.f16.f32 " \
                 "{%0,%1,%2,%3}, {%4,%5,%6,%7}, {%8,%9}, {%0,%1,%2,%3};" \
                 : "+f"((d)[0]), "+f"((d)[1]), "+f"((d)[2]), "+f"((d)[3]) \
                 : "r"(a0), "r"(a1), "r"(a2), "r"(a3), "r"(b0), "r"(b1))

// ============================ transpose + fp16 hi/lo split ============================
// W [K x N] fp32 row-major -> Th/Tl [N x K] fp16 row-major
__device__ __forceinline__ void do_transpose(
    const float* __restrict__ W, int K, int N,
    __half* __restrict__ Th, __half* __restrict__ Tl)
{
    __shared__ float s[32][33];
    const int n0 = blockIdx.x * 32, k0 = blockIdx.y * 32;
    if (n0 >= N || k0 >= K) return;
    const int tr = threadIdx.x >> 3;
    const int tc = (threadIdx.x & 7) * 4;
    const float4 v = *reinterpret_cast<const float4*>(W + (size_t)(k0 + tr) * N + n0 + tc);
    s[tr][tc + 0] = v.x; s[tr][tc + 1] = v.y; s[tr][tc + 2] = v.z; s[tr][tc + 3] = v.w;
    __syncthreads();
    const size_t off = (size_t)(n0 + tr) * K + k0 + tc;
    #pragma unroll
    for (int q = 0; q < 2; ++q) {
        const float x0 = s[tc + q * 2 + 0][tr];
        const float x1 = s[tc + q * 2 + 1][tr];
        const __half h0 = __float2half_rn(x0), h1 = __float2half_rn(x1);
        *reinterpret_cast<__half2*>(Th + off + q * 2) = __halves2half2(h0, h1);
        *reinterpret_cast<__half2*>(Tl + off + q * 2) = __halves2half2(
            __float2half_rn(x0 - __half2float(h0)),
            __float2half_rn(x1 - __half2float(h1)));
    }
}

__global__ void __launch_bounds__(256) transpose_big(
    const float* __restrict__ W1, const float* __restrict__ W2,
    __half* w1h, __half* w1l, __half* w2h, __half* w2l)
{
    if (blockIdx.z == 0) do_transpose(W1, HID, FFN, w1h, w1l);
    else                 do_transpose(W2, FFN, HID, w2h, w2l);
}

__global__ void __launch_bounds__(256) transpose_adapters(
    const float* __restrict__ aw1, const float* __restrict__ aw2,
    const float* __restrict__ bw1, const float* __restrict__ bw2,
    __half* a1h, __half* a1l, __half* a2h, __half* a2l,
    __half* b1h, __half* b1l, __half* b2h, __half* b2l)
{
    switch (blockIdx.z) {
        case 0: do_transpose(aw1, HID, 256, a1h, a1l); break;
        case 1: do_transpose(aw2, 256, HID, a2h, a2l); break;
        case 2: do_transpose(bw1, HID, 512, b1h, b1l); break;
        default: do_transpose(bw2, 512, HID, b2h, b2l); break;
    }
}

// ============================ LayerNorm -> fp32 (optional) + fp16 ============================
__device__ __forceinline__ void block_reduce_sum2(float& s, float& ss) {
    #pragma unroll
    for (int off = 16; off > 0; off >>= 1) {
        s  += __shfl_down_sync(0xffffffffu, s, off);
        ss += __shfl_down_sync(0xffffffffu, ss, off);
    }
    __shared__ float sh_s[8], sh_ss[8];
    int warp = threadIdx.x >> 5, lane = threadIdx.x & 31;
    if (lane == 0) { sh_s[warp] = s; sh_ss[warp] = ss; }
    __syncthreads();
    if (warp == 0) {
        s  = (lane < 8) ? sh_s[lane]  : 0.0f;
        ss = (lane < 8) ? sh_ss[lane] : 0.0f;
        #pragma unroll
        for (int off = 4; off > 0; off >>= 1) {
            s  += __shfl_down_sync(0xffffffffu, s, off);
            ss += __shfl_down_sync(0xffffffffu, ss, off);
        }
        if (lane == 0) { sh_s[0] = s; sh_ss[0] = ss; }
    }
    __syncthreads();
    s = sh_s[0]; ss = sh_ss[0];
}

template <int L>
__global__ void __launch_bounds__(256) ln_kernel(
    const float* __restrict__ in, const float* __restrict__ gw,
    const float* __restrict__ bw, float* __restrict__ outf,
    __half* __restrict__ oh)
{
    constexpr int PER = L / 1024;
    const size_t row = blockIdx.x;
    const float4* inr = reinterpret_cast<const float4*>(in) + row * (L / 4);

    float4 v[PER];
    float s = 0.0f, ss = 0.0f;
    #pragma unroll
    for (int i = 0; i < PER; ++i) {
        v[i] = inr[threadIdx.x + i * 256];
        s  += v[i].x + v[i].y + v[i].z + v[i].w;
        ss += v[i].x * v[i].x + v[i].y * v[i].y + v[i].z * v[i].z + v[i].w * v[i].w;
    }
    block_reduce_sum2(s, ss);
    const float mu  = s * (1.0f / L);
    const float var = ss * (1.0f / L) - mu * mu;
    const float inv = rsqrtf(var + 1e-5f);

    const float4* g4 = reinterpret_cast<const float4*>(gw);
    const float4* b4 = reinterpret_cast<const float4*>(bw);
    float4* outr = outf ? reinterpret_cast<float4*>(outf) + row * (L / 4) : nullptr;
    __half2* ohr = reinterpret_cast<__half2*>(oh) + row * (L / 2);

    #pragma unroll
    for (int i = 0; i < PER; ++i) {
        const int c = threadIdx.x + i * 256;
        const float4 gv = g4[c], bv = b4[c], x = v[i];
        float4 o;
        o.x = (x.x - mu) * inv * gv.x + bv.x;
        o.y = (x.y - mu) * inv * gv.y + bv.y;
        o.z = (x.z - mu) * inv * gv.z + bv.z;
        o.w = (x.w - mu) * inv * gv.w + bv.w;
        if (outr) outr[c] = o;
        ohr[c * 2 + 0] = __halves2half2(__float2half_rn(o.x), __float2half_rn(o.y));
        ohr[c * 2 + 1] = __halves2half2(__float2half_rn(o.z), __float2half_rn(o.w));
    }
}

// ============================ fp16 mma.sync GEMM, 2-term weight split ============================
// C[M,N] = act(A @ (Bh+Bl)^T + bias).  A: [M x K] fp16, Bh/Bl: [N x K] fp16.
// BM=128, BN=128, BK=64, 256 threads (8 warps, 2x4 of 64x32 warp tiles), 3-stage cp.async.
#define GSTAGES 3
#define GSTAGE_BYTES 32768
#define GEMM_SMEM (GSTAGES * GSTAGE_BYTES)

__device__ __forceinline__ void g_load_stage(
    const __half* __restrict__ Ag, const __half* __restrict__ Bhg,
    const __half* __restrict__ Blg, int K, int halfTiles, int t,
    uint32_t sA, int tid)
{
    const int kc = (t % halfTiles) * 64;
    const __half* Bg = (t < halfTiles) ? Bhg : Blg;
    const uint32_t sB = sA + 16384;
    #pragma unroll
    for (int p = 0; p < 4; ++p) {
        const int idx = tid + p * 256;
        const int row = idx >> 3, ch = idx & 7;
        const uint32_t so = row * 128 + ((ch ^ (row & 7)) << 4);
        CP_ASYNC16(sA + so, Ag + (size_t)row * K + kc + ch * 8);
    }
    #pragma unroll
    for (int p = 0; p < 4; ++p) {
        const int idx = tid + p * 256;
        const int row = idx >> 3, ch = idx & 7;
        const uint32_t so = row * 128 + ((ch ^ (row & 7)) << 4);
        CP_ASYNC16(sB + so, Bg + (size_t)row * K + kc + ch * 8);
    }
}

__global__ void __launch_bounds__(256, 2) gemm_fp16(
    const __half* __restrict__ A, const __half* __restrict__ Bh,
    const __half* __restrict__ Bl, const float* __restrict__ bias,
    float* __restrict__ Cf, __half* __restrict__ Ch,
    int M, int N, int K, int do_gelu)
{
    extern __shared__ char smem[];
    const uint32_t sbase = smem_u32(smem);
    const int tid = threadIdx.x, lane = tid & 31, wid = tid >> 5;
    const int warp_m = wid & 1, warp_n = wid >> 1;     // 2 x 4 warps, 64x32 tiles
    const int bm = blockIdx.y, bn = blockIdx.x;

    const __half* Ag  = A  + (size_t)bm * 128 * K;
    const __half* Bhg = Bh + (size_t)bn * 128 * K;
    const __half* Blg = Bl + (size_t)bn * 128 * K;

    uint32_t aAddr[4], bAddr[2];
    const uint32_t hiA = (lane & 16);
    const uint32_t hiB = ((lane & 8) << 1);
    #pragma unroll
    for (int mt = 0; mt < 4; ++mt) {
        const int r = warp_m * 64 + mt * 16 + (lane & 15);
        aAddr[mt] = sbase + r * 128;                 // + swizzled k-offset later
    }
    uint32_t aSw[4], bSw[2];
    #pragma unroll
    for (int mt = 0; mt < 4; ++mt)
        aSw[mt] = (((warp_m * 64 + mt * 16 + (lane & 15)) & 7) << 4);
    #pragma unroll
    for (int ng = 0; ng < 2; ++ng) {
        const int r = warp_n * 32 + ng * 16 + (lane & 7) + ((lane & 16) >> 1);
        bAddr[ng] = sbase + 16384 + r * 128;
        bSw[ng]   = ((r & 7) << 4);
    }

    float acc[4][4][4];
    #pragma unroll
    for (int i = 0; i < 4; ++i)
        #pragma unroll
        for (int j = 0; j < 4; ++j)
            #pragma unroll
            for (int q = 0; q < 4; ++q) acc[i][j][q] = 0.0f;

    const int halfTiles = K >> 6;
    const int ntile = halfTiles * 2;

    g_load_stage(Ag, Bhg, Blg, K, halfTiles, 0, sbase, tid);
    CP_COMMIT();
    g_load_stage(Ag, Bhg, Blg, K, halfTiles, 1, sbase + GSTAGE_BYTES, tid);
    CP_COMMIT();

    for (int t = 0; t < ntile; ++t) {
        CP_WAIT1();
        __syncthreads();
        if (t + 2 < ntile) {
            g_load_stage(Ag, Bhg, Blg, K, halfTiles, t + 2,
                         sbase + ((t + 2) % GSTAGES) * GSTAGE_BYTES, tid);
            CP_COMMIT();
        }
        const uint32_t stOff = (t % GSTAGES) * GSTAGE_BYTES;

        #pragma unroll
        for (int j = 0; j < 4; ++j) {
            uint32_t a[4][4], b[2][4];
            #pragma unroll
            for (int mt = 0; mt < 4; ++mt)
                LDSM4(a[mt][0], a[mt][1], a[mt][2], a[mt][3],
                      aAddr[mt] + stOff + (((uint32_t)(j * 32) + hiA) ^ aSw[mt]));
            #pragma unroll
            for (int ng = 0; ng < 2; ++ng)
                LDSM4(b[ng][0], b[ng][1], b[ng][2], b[ng][3],
                      bAddr[ng] + stOff + (((uint32_t)(j * 32) + hiB) ^ bSw[ng]));
            #pragma unroll
            for (int mt = 0; mt < 4; ++mt)
                #pragma unroll
                for (int nt = 0; nt < 4; ++nt) {
                    const int ng = nt >> 1;
                    if (nt & 1) MMA16816F16(acc[mt][nt], a[mt][0], a[mt][1], a[mt][2], a[mt][3],
                                            b[ng][2], b[ng][3]);
                    else        MMA16816F16(acc[mt][nt], a[mt][0], a[mt][1], a[mt][2], a[mt][3],
                                            b[ng][0], b[ng][1]);
                }
        }
        __syncthreads();
    }

    // ---------------- epilogue ----------------
    const int row0 = bm * 128 + warp_m * 64 + (lane >> 2);
    const int col0 = bn * 128 + warp_n * 32 + (lane & 3) * 2;

    #pragma unroll
    for (int mt = 0; mt < 4; ++mt) {
        #pragma unroll
        for (int nt = 0; nt < 4; ++nt) {
            const int gc = col0 + nt * 8;
            const float bz0 = bias[gc], bz1 = bias[gc + 1];
            float v[4];
            v[0] = acc[mt][nt][0] + bz0;
            v[1] = acc[mt][nt][1] + bz1;
            v[2] = acc[mt][nt][2] + bz0;
            v[3] = acc[mt][nt][3] + bz1;
            if (do_gelu) {
                #pragma unroll
                for (int q = 0; q < 4; ++q) v[q] = gelu_exact(v[q]);
            }
            const size_t r0 = (size_t)(row0 + mt * 16);
            const size_t r1 = r0 + 8;
            if (Cf) {
                *reinterpret_cast<float2*>(Cf + r0 * N + gc) = make_float2(v[0], v[1]);
                *reinterpret_cast<float2*>(Cf + r1 * N + gc) = make_float2(v[2], v[3]);
            }
            if (Ch) {
                *reinterpret_cast<__half2*>(Ch + r0 * N + gc) =
                    __halves2half2(__float2half_rn(v[0]), __float2half_rn(v[1]));
                *reinterpret_cast<__half2*>(Ch + r1 * N + gc) =
                    __halves2half2(__float2half_rn(v[2]), __float2half_rn(v[3]));
            }
        }
    }
}

// ============================ routed combine ============================
__global__ void __launch_bounds__(256) combine_kernel(
    const float* __restrict__ base, const float* __restrict__ ad0,
    const float* __restrict__ ad1,  const float* __restrict__ xn,
    const float* __restrict__ wm,   const int* __restrict__ idx,
    float* __restrict__ out)
{
    const int t = blockIdx.x;
    const float w  = wm[t];
    const float w1 = 1.0f - w;
    const int id = idx[t];
    const float* asel = (id == 0) ? ad0 : ((id == 1) ? ad1 : xn);
    const int off = t * (HID / 4) + threadIdx.x;
    const float4 b = reinterpret_cast<const float4*>(base)[off];
    const float4 a = reinterpret_cast<const float4*>(asel)[off];
    float4 o;
    o.x = b.x * w + a.x * w1;
    o.y = b.y * w + a.y * w1;
    o.z = b.z * w + a.z * w1;
    o.w = b.w * w + a.w * w1;
    reinterpret_cast<float4*>(out)[off] = o;
}

// ============================ launch ============================
extern "C" void kernel_launch(void* const* d_in, const int* in_sizes, int n_in,
                              void* d_out, int out_size)
{
    const float* x        = (const float*)d_in[0];
    const float* wm       = (const float*)d_in[1];
    const int*   widx     = (const int*)  d_in[2];
    const float* ln_in_g  = (const float*)d_in[3];
    const float* ln_in_b  = (const float*)d_in[4];
    const float* W1       = (const float*)d_in[5];
    const float* b1       = (const float*)d_in[6];
    const float* ln_h_g   = (const float*)d_in[7];
    const float* ln_h_b   = (const float*)d_in[8];
    const float* W2       = (const float*)d_in[9];
    const float* b2       = (const float*)d_in[10];
    const float* a256_w1  = (const float*)d_in[11];
    const float* a256_b1  = (const float*)d_in[12];
    const float* a256_w2  = (const float*)d_in[13];
    const float* a256_b2  = (const float*)d_in[14];
    const float* a512_w1  = (const float*)d_in[15];
    const float* a512_b1  = (const float*)d_in[16];
    const float* a512_w2  = (const float*)d_in[17];
    const float* a512_b2  = (const float*)d_in[18];
    float* out = (float*)d_out;

    cudaFuncSetAttribute(gemm_fp16, cudaFuncAttributeMaxDynamicSharedMemorySize, GEMM_SMEM);

    float *xnorm, *h, *base, *ad0, *ad1;
    __half *xnh, *hnh, *t0h, *t1h;
    __half *w1h, *w1l, *w2h, *w2l, *a1h, *a1l, *a2h, *a2l, *b1h, *b1l, *b2h, *b2l;
    cudaGetSymbolAddress((void**)&xnorm, g_xnorm);
    cudaGetSymbolAddress((void**)&h,     g_h);
    cudaGetSymbolAddress((void**)&base,  g_base);
    cudaGetSymbolAddress((void**)&ad0,   g_ad0);
    cudaGetSymbolAddress((void**)&ad1,   g_ad1);
    cudaGetSymbolAddress((void**)&xnh,   g_xnh);
    cudaGetSymbolAddress((void**)&hnh,   g_hnh);
    cudaGetSymbolAddress((void**)&t0h,   g_t0h);
    cudaGetSymbolAddress((void**)&t1h,   g_t1h);
    cudaGetSymbolAddress((void**)&w1h,   g_w1t_h);  cudaGetSymbolAddress((void**)&w1l, g_w1t_l);
    cudaGetSymbolAddress((void**)&w2h,   g_w2t_h);  cudaGetSymbolAddress((void**)&w2l, g_w2t_l);
    cudaGetSymbolAddress((void**)&a1h,   g_aw1t_h); cudaGetSymbolAddress((void**)&a1l, g_aw1t_l);
    cudaGetSymbolAddress((void**)&a2h,   g_aw2t_h); cudaGetSymbolAddress((void**)&a2l, g_aw2t_l);
    cudaGetSymbolAddress((void**)&b1h,   g_bw1t_h); cudaGetSymbolAddress((void**)&b1l, g_bw1t_l);
    cudaGetSymbolAddress((void**)&b2h,   g_bw2t_h); cudaGetSymbolAddress((void**)&b2l, g_bw2t_l);

    // L0, L1: weight transposes + fp16 hi/lo split
    transpose_big<<<dim3(128, 128, 2), 256>>>(W1, W2, w1h, w1l, w2h, w2l);
    transpose_adapters<<<dim3(32, 32, 4), 256>>>(a256_w1, a256_w2, a512_w1, a512_w2,
                                                 a1h, a1l, a2h, a2l, b1h, b1l, b2h, b2l);

    // L2: x_norm = LN(x) -> fp32 + fp16
    ln_kernel<HID><<<TOKENS, 256>>>(x, ln_in_g, ln_in_b, xnorm, xnh);

    // L3: h = gelu(x_norm @ W1 + b1)   [8192 x 4096, K=1024]
    gemm_fp16<<<dim3(FFN / 128, TOKENS / 128), 256, GEMM_SMEM>>>(
        xnh, w1h, w1l, b1, h, nullptr, TOKENS, FFN, HID, 1);

    // L4: h_norm = LN(h) -> fp16 only
    ln_kernel<FFN><<<TOKENS, 256>>>(h, ln_h_g, ln_h_b, nullptr, hnh);

    // L5 (ncu target): base = h_norm @ W2 + b2   [8192 x 1024, K=4096]
    gemm_fp16<<<dim3(HID / 128, TOKENS / 128), 256, GEMM_SMEM>>>(
        hnh, w2h, w2l, b2, base, nullptr, TOKENS, HID, FFN, 0);

    // adapters
    gemm_fp16<<<dim3(256 / 128, TOKENS / 128), 256, GEMM_SMEM>>>(
        xnh, a1h, a1l, a256_b1, nullptr, t0h, TOKENS, 256, HID, 1);
    gemm_fp16<<<dim3(HID / 128, TOKENS / 128), 256, GEMM_SMEM>>>(
        t0h, a2h, a2l, a256_b2, ad0, nullptr, TOKENS, HID, 256, 0);
    gemm_fp16<<<dim3(512 / 128, TOKENS / 128), 256, GEMM_SMEM>>>(
        xnh, b1h, b1l, a512_b1, nullptr, t1h, TOKENS, 512, HID, 1);
    gemm_fp16<<<dim3(HID / 128, TOKENS / 128), 256, GEMM_SMEM>>>(
        t1h, b2h, b2l, a512_b2, ad1, nullptr, TOKENS, HID, 512, 0);

    // combine
    combine_kernel<<<TOKENS, 256>>>(base, ad0, ad1, xnorm, wm, widx, out);
}

// round 5
// speedup vs baseline: 6.9715x; 1.7744x over previous
#include <cuda_runtime.h>
#include <cuda_fp16.h>
#include <math.h>
#include <stdint.h>

#define TOKENS 8192
#define HID    1024
#define FFN    4096

// ============================ scratch (device globals) ============================
__device__ float  g_xnorm[TOKENS * HID];          // fp32 x_norm (combine)
__device__ __half g_xnh[TOKENS * HID];            // fp16 x_norm (GEMM A)
__device__ float  g_h[TOKENS * FFN];              // fp32 h pre-LN
__device__ __half g_hnh[TOKENS * FFN];            // fp16 h_norm
__device__ float  g_base[TOKENS * HID], g_ad0[TOKENS * HID], g_ad1[TOKENS * HID];
__device__ __half g_t0h[TOKENS * 256];
__device__ __half g_t1h[TOKENS * 512];
// weight planes: W^T [N x K] fp16 (single plane)
__device__ __half g_w1t[FFN * HID];
__device__ __half g_w2t[HID * FFN];
__device__ __half g_aw1t[256 * HID];
__device__ __half g_aw2t[HID * 256];
__device__ __half g_bw1t[512 * HID];
__device__ __half g_bw2t[HID * 512];

__device__ __forceinline__ float gelu_exact(float x) {
    return 0.5f * x * (1.0f + erff(x * 0.7071067811865475f));
}
__device__ __forceinline__ uint32_t smem_u32(const void* p) {
    uint32_t a;
    asm("{ .reg .u64 t; cvta.to.shared.u64 t, %1; cvt.u32.u64 %0, t; }" : "=r"(a) : "l"(p));
    return a;
}

#define CP_ASYNC16(s, g) \
    asm volatile("cp.async.cg.shared.global [%0], [%1], 16;" :: "r"(s), "l"(g))
#define CP_COMMIT() asm volatile("cp.async.commit_group;")
#define CP_WAIT1()  asm volatile("cp.async.wait_group 1;")

#define LDSM4(r0, r1, r2, r3, addr) \
    asm volatile("ldmatrix.sync.aligned.m8n8.x4.shared.b16 {%0,%1,%2,%3}, [%4];" \
                 : "=r"(r0), "=r"(r1), "=r"(r2), "=r"(r3) : "r"(addr))

#define MMA16816F16(d, a0, a1, a2, a3, b0, b1) \
    asm volatile("mma.sync.aligned.m16n8k16.row.col.f32.f16.f16.f32 " \
                 "{%0,%1,%2,%3}, {%4,%5,%6,%7}, {%8,%9}, {%0,%1,%2,%3};" \
                 : "+f"((d)[0]), "+f"((d)[1]), "+f"((d)[2]), "+f"((d)[3]) \
                 : "r"(a0), "r"(a1), "r"(a2), "r"(a3), "r"(b0), "r"(b1))

// ============================ transpose to fp16 W^T ============================
// W [K x N] fp32 row-major -> T [N x K] fp16 row-major
__device__ __forceinline__ void do_transpose(
    const float* __restrict__ W, int K, int N, __half* __restrict__ T)
{
    __shared__ float s[32][33];
    const int n0 = blockIdx.x * 32, k0 = blockIdx.y * 32;
    if (n0 >= N || k0 >= K) return;
    const int tr = threadIdx.x >> 3;
    const int tc = (threadIdx.x & 7) * 4;
    const float4 v = *reinterpret_cast<const float4*>(W + (size_t)(k0 + tr) * N + n0 + tc);
    s[tr][tc + 0] = v.x; s[tr][tc + 1] = v.y; s[tr][tc + 2] = v.z; s[tr][tc + 3] = v.w;
    __syncthreads();
    const size_t off = (size_t)(n0 + tr) * K + k0 + tc;
    #pragma unroll
    for (int q = 0; q < 2; ++q) {
        const float x0 = s[tc + q * 2 + 0][tr];
        const float x1 = s[tc + q * 2 + 1][tr];
        *reinterpret_cast<__half2*>(T + off + q * 2) =
            __halves2half2(__float2half_rn(x0), __float2half_rn(x1));
    }
}

__global__ void __launch_bounds__(256) transpose_big(
    const float* __restrict__ W1, const float* __restrict__ W2,
    __half* w1t, __half* w2t)
{
    if (blockIdx.z == 0) do_transpose(W1, HID, FFN, w1t);
    else                 do_transpose(W2, FFN, HID, w2t);
}

__global__ void __launch_bounds__(256) transpose_adapters(
    const float* __restrict__ aw1, const float* __restrict__ aw2,
    const float* __restrict__ bw1, const float* __restrict__ bw2,
    __half* a1t, __half* a2t, __half* b1t, __half* b2t)
{
    switch (blockIdx.z) {
        case 0: do_transpose(aw1, HID, 256, a1t); break;
        case 1: do_transpose(aw2, 256, HID, a2t); break;
        case 2: do_transpose(bw1, HID, 512, b1t); break;
        default: do_transpose(bw2, 512, HID, b2t); break;
    }
}

// ============================ LayerNorm -> fp32 (optional) + fp16 ============================
__device__ __forceinline__ void block_reduce_sum2(float& s, float& ss) {
    #pragma unroll
    for (int off = 16; off > 0; off >>= 1) {
        s  += __shfl_down_sync(0xffffffffu, s, off);
        ss += __shfl_down_sync(0xffffffffu, ss, off);
    }
    __shared__ float sh_s[8], sh_ss[8];
    int warp = threadIdx.x >> 5, lane = threadIdx.x & 31;
    if (lane == 0) { sh_s[warp] = s; sh_ss[warp] = ss; }
    __syncthreads();
    if (warp == 0) {
        s  = (lane < 8) ? sh_s[lane]  : 0.0f;
        ss = (lane < 8) ? sh_ss[lane] : 0.0f;
        #pragma unroll
        for (int off = 4; off > 0; off >>= 1) {
            s  += __shfl_down_sync(0xffffffffu, s, off);
            ss += __shfl_down_sync(0xffffffffu, ss, off);
        }
        if (lane == 0) { sh_s[0] = s; sh_ss[0] = ss; }
    }
    __syncthreads();
    s = sh_s[0]; ss = sh_ss[0];
}

template <int L>
__global__ void __launch_bounds__(256) ln_kernel(
    const float* __restrict__ in, const float* __restrict__ gw,
    const float* __restrict__ bw, float* __restrict__ outf,
    __half* __restrict__ oh)
{
    constexpr int PER = L / 1024;
    const size_t row = blockIdx.x;
    const float4* inr = reinterpret_cast<const float4*>(in) + row * (L / 4);

    float4 v[PER];
    float s = 0.0f, ss = 0.0f;
    #pragma unroll
    for (int i = 0; i < PER; ++i) {
        v[i] = inr[threadIdx.x + i * 256];
        s  += v[i].x + v[i].y + v[i].z + v[i].w;
        ss += v[i].x * v[i].x + v[i].y * v[i].y + v[i].z * v[i].z + v[i].w * v[i].w;
    }
    block_reduce_sum2(s, ss);
    const float mu  = s * (1.0f / L);
    const float var = ss * (1.0f / L) - mu * mu;
    const float inv = rsqrtf(var + 1e-5f);

    const float4* g4 = reinterpret_cast<const float4*>(gw);
    const float4* b4 = reinterpret_cast<const float4*>(bw);
    float4* outr = outf ? reinterpret_cast<float4*>(outf) + row * (L / 4) : nullptr;
    __half2* ohr = reinterpret_cast<__half2*>(oh) + row * (L / 2);

    #pragma unroll
    for (int i = 0; i < PER; ++i) {
        const int c = threadIdx.x + i * 256;
        const float4 gv = g4[c], bv = b4[c], x = v[i];
        float4 o;
        o.x = (x.x - mu) * inv * gv.x + bv.x;
        o.y = (x.y - mu) * inv * gv.y + bv.y;
        o.z = (x.z - mu) * inv * gv.z + bv.z;
        o.w = (x.w - mu) * inv * gv.w + bv.w;
        if (outr) outr[c] = o;
        ohr[c * 2 + 0] = __halves2half2(__float2half_rn(o.x), __float2half_rn(o.y));
        ohr[c * 2 + 1] = __halves2half2(__float2half_rn(o.z), __float2half_rn(o.w));
    }
}

// ============================ fp16 mma.sync GEMM (plain) ============================
// C[M,N] = act(A @ B^T + bias).  A: [M x K] fp16, B: [N x K] fp16.
// BM=128, BN=128, BK=64, 256 threads (8 warps, 2x4 of 64x32 warp tiles), 3-stage cp.async.
#define GSTAGES 3
#define GSTAGE_BYTES 32768
#define GEMM_SMEM (GSTAGES * GSTAGE_BYTES)

__device__ __forceinline__ void g_load_stage(
    const __half* __restrict__ Ag, const __half* __restrict__ Bg,
    int K, int kc, uint32_t sA, int tid)
{
    const uint32_t sB = sA + 16384;
    #pragma unroll
    for (int p = 0; p < 4; ++p) {
        const int idx = tid + p * 256;
        const int row = idx >> 3, ch = idx & 7;
        const uint32_t so = row * 128 + ((ch ^ (row & 7)) << 4);
        CP_ASYNC16(sA + so, Ag + (size_t)row * K + kc + ch * 8);
    }
    #pragma unroll
    for (int p = 0; p < 4; ++p) {
        const int idx = tid + p * 256;
        const int row = idx >> 3, ch = idx & 7;
        const uint32_t so = row * 128 + ((ch ^ (row & 7)) << 4);
        CP_ASYNC16(sB + so, Bg + (size_t)row * K + kc + ch * 8);
    }
}

__global__ void __launch_bounds__(256, 2) gemm_fp16(
    const __half* __restrict__ A, const __half* __restrict__ B,
    const float* __restrict__ bias,
    float* __restrict__ Cf, __half* __restrict__ Ch,
    int M, int N, int K, int do_gelu)
{
    extern __shared__ char smem[];
    const uint32_t sbase = smem_u32(smem);
    const int tid = threadIdx.x, lane = tid & 31, wid = tid >> 5;
    const int warp_m = wid & 1, warp_n = wid >> 1;     // 2 x 4 warps, 64x32 tiles
    const int bm = blockIdx.y, bn = blockIdx.x;

    const __half* Ag = A + (size_t)bm * 128 * K;
    const __half* Bg = B + (size_t)bn * 128 * K;

    uint32_t aAddr[4], bAddr[2], aSw[4], bSw[2];
    const uint32_t hiA = (lane & 16);
    const uint32_t hiB = ((lane & 8) << 1);
    #pragma unroll
    for (int mt = 0; mt < 4; ++mt) {
        const int r = warp_m * 64 + mt * 16 + (lane & 15);
        aAddr[mt] = sbase + r * 128;
        aSw[mt]   = ((r & 7) << 4);
    }
    #pragma unroll
    for (int ng = 0; ng < 2; ++ng) {
        const int r = warp_n * 32 + ng * 16 + (lane & 7) + ((lane & 16) >> 1);
        bAddr[ng] = sbase + 16384 + r * 128;
        bSw[ng]   = ((r & 7) << 4);
    }

    float acc[4][4][4];
    #pragma unroll
    for (int i = 0; i < 4; ++i)
        #pragma unroll
        for (int j = 0; j < 4; ++j)
            #pragma unroll
            for (int q = 0; q < 4; ++q) acc[i][j][q] = 0.0f;

    const int ntile = K >> 6;

    g_load_stage(Ag, Bg, K, 0, sbase, tid);
    CP_COMMIT();
    g_load_stage(Ag, Bg, K, 64, sbase + GSTAGE_BYTES, tid);
    CP_COMMIT();

    for (int t = 0; t < ntile; ++t) {
        CP_WAIT1();
        __syncthreads();
        if (t + 2 < ntile) {
            g_load_stage(Ag, Bg, K, (t + 2) * 64,
                         sbase + ((t + 2) % GSTAGES) * GSTAGE_BYTES, tid);
            CP_COMMIT();
        }
        const uint32_t stOff = (t % GSTAGES) * GSTAGE_BYTES;

        #pragma unroll
        for (int j = 0; j < 4; ++j) {
            uint32_t a[4][4], b[2][4];
            #pragma unroll
            for (int mt = 0; mt < 4; ++mt)
                LDSM4(a[mt][0], a[mt][1], a[mt][2], a[mt][3],
                      aAddr[mt] + stOff + (((uint32_t)(j * 32) + hiA) ^ aSw[mt]));
            #pragma unroll
            for (int ng = 0; ng < 2; ++ng)
                LDSM4(b[ng][0], b[ng][1], b[ng][2], b[ng][3],
                      bAddr[ng] + stOff + (((uint32_t)(j * 32) + hiB) ^ bSw[ng]));
            #pragma unroll
            for (int mt = 0; mt < 4; ++mt)
                #pragma unroll
                for (int nt = 0; nt < 4; ++nt) {
                    const int ng = nt >> 1;
                    if (nt & 1) MMA16816F16(acc[mt][nt], a[mt][0], a[mt][1], a[mt][2], a[mt][3],
                                            b[ng][2], b[ng][3]);
                    else        MMA16816F16(acc[mt][nt], a[mt][0], a[mt][1], a[mt][2], a[mt][3],
                                            b[ng][0], b[ng][1]);
                }
        }
        __syncthreads();
    }

    // ---------------- epilogue ----------------
    const int row0 = bm * 128 + warp_m * 64 + (lane >> 2);
    const int col0 = bn * 128 + warp_n * 32 + (lane & 3) * 2;

    #pragma unroll
    for (int mt = 0; mt < 4; ++mt) {
        #pragma unroll
        for (int nt = 0; nt < 4; ++nt) {
            const int gc = col0 + nt * 8;
            const float bz0 = bias[gc], bz1 = bias[gc + 1];
            float v[4];
            v[0] = acc[mt][nt][0] + bz0;
            v[1] = acc[mt][nt][1] + bz1;
            v[2] = acc[mt][nt][2] + bz0;
            v[3] = acc[mt][nt][3] + bz1;
            if (do_gelu) {
                #pragma unroll
                for (int q = 0; q < 4; ++q) v[q] = gelu_exact(v[q]);
            }
            const size_t r0 = (size_t)(row0 + mt * 16);
            const size_t r1 = r0 + 8;
            if (Cf) {
                *reinterpret_cast<float2*>(Cf + r0 * N + gc) = make_float2(v[0], v[1]);
                *reinterpret_cast<float2*>(Cf + r1 * N + gc) = make_float2(v[2], v[3]);
            }
            if (Ch) {
                *reinterpret_cast<__half2*>(Ch + r0 * N + gc) =
                    __halves2half2(__float2half_rn(v[0]), __float2half_rn(v[1]));
                *reinterpret_cast<__half2*>(Ch + r1 * N + gc) =
                    __halves2half2(__float2half_rn(v[2]), __float2half_rn(v[3]));
            }
        }
    }
}

// ============================ routed combine ============================
__global__ void __launch_bounds__(256) combine_kernel(
    const float* __restrict__ base, const float* __restrict__ ad0,
    const float* __restrict__ ad1,  const float* __restrict__ xn,
    const float* __restrict__ wm,   const int* __restrict__ idx,
    float* __restrict__ out)
{
    const int t = blockIdx.x;
    const float w  = wm[t];
    const float w1 = 1.0f - w;
    const int id = idx[t];
    const float* asel = (id == 0) ? ad0 : ((id == 1) ? ad1 : xn);
    const int off = t * (HID / 4) + threadIdx.x;
    const float4 b = reinterpret_cast<const float4*>(base)[off];
    const float4 a = reinterpret_cast<const float4*>(asel)[off];
    float4 o;
    o.x = b.x * w + a.x * w1;
    o.y = b.y * w + a.y * w1;
    o.z = b.z * w + a.z * w1;
    o.w = b.w * w + a.w * w1;
    reinterpret_cast<float4*>(out)[off] = o;
}

// ============================ launch ============================
extern "C" void kernel_launch(void* const* d_in, const int* in_sizes, int n_in,
                              void* d_out, int out_size)
{
    const float* x        = (const float*)d_in[0];
    const float* wm       = (const float*)d_in[1];
    const int*   widx     = (const int*)  d_in[2];
    const float* ln_in_g  = (const float*)d_in[3];
    const float* ln_in_b  = (const float*)d_in[4];
    const float* W1       = (const float*)d_in[5];
    const float* b1       = (const float*)d_in[6];
    const float* ln_h_g   = (const float*)d_in[7];
    const float* ln_h_b   = (const float*)d_in[8];
    const float* W2       = (const float*)d_in[9];
    const float* b2       = (const float*)d_in[10];
    const float* a256_w1  = (const float*)d_in[11];
    const float* a256_b1  = (const float*)d_in[12];
    const float* a256_w2  = (const float*)d_in[13];
    const float* a256_b2  = (const float*)d_in[14];
    const float* a512_w1  = (const float*)d_in[15];
    const float* a512_b1  = (const float*)d_in[16];
    const float* a512_w2  = (const float*)d_in[17];
    const float* a512_b2  = (const float*)d_in[18];
    float* out = (float*)d_out;

    cudaFuncSetAttribute(gemm_fp16, cudaFuncAttributeMaxDynamicSharedMemorySize, GEMM_SMEM);

    float *xnorm, *h, *base, *ad0, *ad1;
    __half *xnh, *hnh, *t0h, *t1h;
    __half *w1t, *w2t, *a1t, *a2t, *b1t, *b2t;
    cudaGetSymbolAddress((void**)&xnorm, g_xnorm);
    cudaGetSymbolAddress((void**)&h,     g_h);
    cudaGetSymbolAddress((void**)&base,  g_base);
    cudaGetSymbolAddress((void**)&ad0,   g_ad0);
    cudaGetSymbolAddress((void**)&ad1,   g_ad1);
    cudaGetSymbolAddress((void**)&xnh,   g_xnh);
    cudaGetSymbolAddress((void**)&hnh,   g_hnh);
    cudaGetSymbolAddress((void**)&t0h,   g_t0h);
    cudaGetSymbolAddress((void**)&t1h,   g_t1h);
    cudaGetSymbolAddress((void**)&w1t,   g_w1t);
    cudaGetSymbolAddress((void**)&w2t,   g_w2t);
    cudaGetSymbolAddress((void**)&a1t,   g_aw1t);
    cudaGetSymbolAddress((void**)&a2t,   g_aw2t);
    cudaGetSymbolAddress((void**)&b1t,   g_bw1t);
    cudaGetSymbolAddress((void**)&b2t,   g_bw2t);

    // L0, L1: weight transposes -> fp16 W^T
    transpose_big<<<dim3(128, 128, 2), 256>>>(W1, W2, w1t, w2t);
    transpose_adapters<<<dim3(32, 32, 4), 256>>>(a256_w1, a256_w2, a512_w1, a512_w2,
                                                 a1t, a2t, b1t, b2t);

    // L2: x_norm = LN(x) -> fp32 + fp16
    ln_kernel<HID><<<TOKENS, 256>>>(x, ln_in_g, ln_in_b, xnorm, xnh);

    // L3: h = gelu(x_norm @ W1 + b1)   [8192 x 4096, K=1024]
    gemm_fp16<<<dim3(FFN / 128, TOKENS / 128), 256, GEMM_SMEM>>>(
        xnh, w1t, b1, h, nullptr, TOKENS, FFN, HID, 1);

    // L4: h_norm = LN(h) -> fp16 only
    ln_kernel<FFN><<<TOKENS, 256>>>(h, ln_h_g, ln_h_b, nullptr, hnh);

    // L5 (ncu target): base = h_norm @ W2 + b2   [8192 x 1024, K=4096]
    gemm_fp16<<<dim3(HID / 128, TOKENS / 128), 256, GEMM_SMEM>>>(
        hnh, w2t, b2, base, nullptr, TOKENS, HID, FFN, 0);

    // adapters
    gemm_fp16<<<dim3(256 / 128, TOKENS / 128), 256, GEMM_SMEM>>>(
        xnh, a1t, a256_b1, nullptr, t0h, TOKENS, 256, HID, 1);
    gemm_fp16<<<dim3(HID / 128, TOKENS / 128), 256, GEMM_SMEM>>>(
        t0h, a2t, a256_b2, ad0, nullptr, TOKENS, HID, 256, 0);
    gemm_fp16<<<dim3(512 / 128, TOKENS / 128), 256, GEMM_SMEM>>>(
        xnh, b1t, a512_b1, nullptr, t1h, TOKENS, 512, HID, 1);
    gemm_fp16<<<dim3(HID / 128, TOKENS / 128), 256, GEMM_SMEM>>>(
        t1h, b2t, a512_b2, ad1, nullptr, TOKENS, HID, 512, 0);

    // combine
    combine_kernel<<<TOKENS, 256>>>(base, ad0, ad1, xnorm, wm, widx, out);
}

// round 6
// speedup vs baseline: 7.7109x; 1.1061x over previous
#include <cuda_runtime.h>
#include <cuda_fp16.h>
#include <math.h>
#include <stdint.h>

#define TOKENS 8192
#define HID    1024
#define FFN    4096
#define NUP    4864      // 4096 + 256 + 512 fused up-projection width

// ============================ scratch (device globals) ============================
__device__ float  g_xnorm[TOKENS * HID];
__device__ __half g_xnh[TOKENS * HID];
__device__ float  g_h[TOKENS * FFN];
__device__ __half g_hnh[TOKENS * FFN];
__device__ float  g_base[TOKENS * HID], g_ad0[TOKENS * HID], g_ad1[TOKENS * HID];
__device__ __half g_t0h[TOKENS * 256];
__device__ __half g_t1h[TOKENS * 512];
__device__ __half g_wup[NUP * HID];     // [W1 | a256_w1 | a512_w1]^T  fp16
__device__ float  g_bup[NUP];           // [b1 | a256_b1 | a512_b1]
__device__ __half g_w2t[HID * FFN];
__device__ __half g_a2t[HID * 256];
__device__ __half g_b2t[HID * 512];

__device__ __forceinline__ float gelu_exact(float x) {
    return 0.5f * x * (1.0f + erff(x * 0.7071067811865475f));
}
__device__ __forceinline__ uint32_t smem_u32(const void* p) {
    uint32_t a;
    asm("{ .reg .u64 t; cvta.to.shared.u64 t, %1; cvt.u32.u64 %0, t; }" : "=r"(a) : "l"(p));
    return a;
}

#define CP_ASYNC16(s, g) \
    asm volatile("cp.async.cg.shared.global [%0], [%1], 16;" :: "r"(s), "l"(g))
#define CP_COMMIT() asm volatile("cp.async.commit_group;")
#define CP_WAIT1()  asm volatile("cp.async.wait_group 1;")
#define CP_WAIT0()  asm volatile("cp.async.wait_group 0;")

#define LDSM4(r0, r1, r2, r3, addr) \
    asm volatile("ldmatrix.sync.aligned.m8n8.x4.shared.b16 {%0,%1,%2,%3}, [%4];" \
                 : "=r"(r0), "=r"(r1), "=r"(r2), "=r"(r3) : "r"(addr))

#define MMA16816F16(d, a0, a1, a2, a3, b0, b1) \
    asm volatile("mma.sync.aligned.m16n8k16.row.col.f32.f16.f16.f32 " \
                 "{%0,%1,%2,%3}, {%4,%5,%6,%7}, {%8,%9}, {%0,%1,%2,%3};" \
                 : "+f"((d)[0]), "+f"((d)[1]), "+f"((d)[2]), "+f"((d)[3]) \
                 : "r"(a0), "r"(a1), "r"(a2), "r"(a3), "r"(b0), "r"(b1))

// ============================ transpose to fp16 W^T (with row offset) ============================
// W [K x N] fp32 row-major -> T rows [rowOff + n], row stride K: T[(rowOff+n)*K + k]
__device__ __forceinline__ void do_transpose(
    const float* __restrict__ W, int K, int N, __half* __restrict__ T, int rowOff)
{
    __shared__ float s[32][33];
    const int n0 = blockIdx.x * 32, k0 = blockIdx.y * 32;
    if (n0 >= N || k0 >= K) return;
    const int tr = threadIdx.x >> 3;
    const int tc = (threadIdx.x & 7) * 4;
    const float4 v = *reinterpret_cast<const float4*>(W + (size_t)(k0 + tr) * N + n0 + tc);
    s[tr][tc + 0] = v.x; s[tr][tc + 1] = v.y; s[tr][tc + 2] = v.z; s[tr][tc + 3] = v.w;
    __syncthreads();
    const size_t off = (size_t)(rowOff + n0 + tr) * K + k0 + tc;
    #pragma unroll
    for (int q = 0; q < 2; ++q) {
        const float x0 = s[tc + q * 2 + 0][tr];
        const float x1 = s[tc + q * 2 + 1][tr];
        *reinterpret_cast<__half2*>(T + off + q * 2) =
            __halves2half2(__float2half_rn(x0), __float2half_rn(x1));
    }
}

__global__ void __launch_bounds__(256) transpose_big(
    const float* __restrict__ W1, const float* __restrict__ W2,
    __half* wup, __half* w2t)
{
    if (blockIdx.z == 0) do_transpose(W1, HID, FFN, wup, 0);
    else                 do_transpose(W2, FFN, HID, w2t, 0);
}

__global__ void __launch_bounds__(256) transpose_adapters(
    const float* __restrict__ aw1, const float* __restrict__ aw2,
    const float* __restrict__ bw1, const float* __restrict__ bw2,
    __half* wup, __half* a2t, __half* b2t)
{
    switch (blockIdx.z) {
        case 0: do_transpose(aw1, HID, 256, wup, 4096); break;
        case 1: do_transpose(aw2, 256, HID, a2t, 0);    break;
        case 2: do_transpose(bw1, HID, 512, wup, 4352); break;
        default: do_transpose(bw2, 512, HID, b2t, 0);   break;
    }
}

__global__ void __launch_bounds__(256) bias_concat(
    const float* __restrict__ b1, const float* __restrict__ ab1,
    const float* __restrict__ bb1, float* __restrict__ out)
{
    const int i = blockIdx.x * 256 + threadIdx.x;
    if (i >= NUP) return;
    float v;
    if (i < 4096) v = b1[i];
    else if (i < 4352) v = ab1[i - 4096];
    else v = bb1[i - 4352];
    out[i] = v;
}

// ============================ LayerNorm -> fp32 (optional) + fp16 ============================
__device__ __forceinline__ void block_reduce_sum2(float& s, float& ss) {
    #pragma unroll
    for (int off = 16; off > 0; off >>= 1) {
        s  += __shfl_down_sync(0xffffffffu, s, off);
        ss += __shfl_down_sync(0xffffffffu, ss, off);
    }
    __shared__ float sh_s[8], sh_ss[8];
    int warp = threadIdx.x >> 5, lane = threadIdx.x & 31;
    if (lane == 0) { sh_s[warp] = s; sh_ss[warp] = ss; }
    __syncthreads();
    if (warp == 0) {
        s  = (lane < 8) ? sh_s[lane]  : 0.0f;
        ss = (lane < 8) ? sh_ss[lane] : 0.0f;
        #pragma unroll
        for (int off = 4; off > 0; off >>= 1) {
            s  += __shfl_down_sync(0xffffffffu, s, off);
            ss += __shfl_down_sync(0xffffffffu, ss, off);
        }
        if (lane == 0) { sh_s[0] = s; sh_ss[0] = ss; }
    }
    __syncthreads();
    s = sh_s[0]; ss = sh_ss[0];
}

template <int L>
__global__ void __launch_bounds__(256) ln_kernel(
    const float* __restrict__ in, const float* __restrict__ gw,
    const float* __restrict__ bw, float* __restrict__ outf,
    __half* __restrict__ oh)
{
    constexpr int PER = L / 1024;
    const size_t row = blockIdx.x;
    const float4* inr = reinterpret_cast<const float4*>(in) + row * (L / 4);

    float4 v[PER];
    float s = 0.0f, ss = 0.0f;
    #pragma unroll
    for (int i = 0; i < PER; ++i) {
        v[i] = inr[threadIdx.x + i * 256];
        s  += v[i].x + v[i].y + v[i].z + v[i].w;
        ss += v[i].x * v[i].x + v[i].y * v[i].y + v[i].z * v[i].z + v[i].w * v[i].w;
    }
    block_reduce_sum2(s, ss);
    const float mu  = s * (1.0f / L);
    const float var = ss * (1.0f / L) - mu * mu;
    const float inv = rsqrtf(var + 1e-5f);

    const float4* g4 = reinterpret_cast<const float4*>(gw);
    const float4* b4 = reinterpret_cast<const float4*>(bw);
    float4* outr = outf ? reinterpret_cast<float4*>(outf) + row * (L / 4) : nullptr;
    __half2* ohr = reinterpret_cast<__half2*>(oh) + row * (L / 2);

    #pragma unroll
    for (int i = 0; i < PER; ++i) {
        const int c = threadIdx.x + i * 256;
        const float4 gv = g4[c], bv = b4[c], x = v[i];
        float4 o;
        o.x = (x.x - mu) * inv * gv.x + bv.x;
        o.y = (x.y - mu) * inv * gv.y + bv.y;
        o.z = (x.z - mu) * inv * gv.z + bv.z;
        o.w = (x.w - mu) * inv * gv.w + bv.w;
        if (outr) outr[c] = o;
        ohr[c * 2 + 0] = __halves2half2(__float2half_rn(o.x), __float2half_rn(o.y));
        ohr[c * 2 + 1] = __halves2half2(__float2half_rn(o.z), __float2half_rn(o.w));
    }
}

// ============================ fp16 mma.sync GEMM body ============================
// C = act(A @ B^T + bias). A: [M x K] fp16, B: [N x K] fp16. 128x128 tile, BK=64,
// 256 threads (8 warps, 2x4 of 64x32 warp tiles), 3-stage cp.async.
#define GSTAGES 3
#define GSTAGE_BYTES 32768
#define GEMM_SMEM (GSTAGES * GSTAGE_BYTES)

__device__ __forceinline__ void issue_tile(
    uint32_t dstA, uint32_t dstB,
    const __half* gA, const __half* gB, size_t gStride)
{
    #pragma unroll
    for (int p = 0; p < 4; ++p)
        CP_ASYNC16(dstA + p * 4096, gA + p * gStride);
    #pragma unroll
    for (int p = 0; p < 4; ++p)
        CP_ASYNC16(dstB + p * 4096, gB + p * gStride);
    CP_COMMIT();
}

__device__ __forceinline__ void gemm_body(
    const __half* __restrict__ A, const __half* __restrict__ B,
    const float* __restrict__ bias,
    float* Cf, __half* Ch, __half* Ch2,
    int N, int K, int do_gelu, int fusedUp, int bm, int bn)
{
    extern __shared__ char smem[];
    const uint32_t sbase = smem_u32(smem);
    const int tid = threadIdx.x, lane = tid & 31, wid = tid >> 5;
    const int warp_m = wid & 1, warp_n = wid >> 1;

    // --- cp.async addressing (loop-invariant) ---
    const int lrow = tid >> 3;                 // 0..31
    const int lch  = tid & 7;
    const uint32_t sOffA = (uint32_t)lrow * 128 + ((lch ^ (lrow & 7)) << 4);
    const uint32_t sOffB = sOffA + 16384;
    const __half* gA = A + (size_t)(bm * 128 + lrow) * K + lch * 8;
    const __half* gB = B + (size_t)(bn * 128 + lrow) * K + lch * 8;
    const size_t gStride = (size_t)32 * K;

    // --- ldsm addressing ---
    uint32_t aAddr[4], bAddr[2], aSw[4], bSw[2];
    const uint32_t hiA = (lane & 16);
    const uint32_t hiB = ((lane & 8) << 1);
    #pragma unroll
    for (int mt = 0; mt < 4; ++mt) {
        const int r = warp_m * 64 + mt * 16 + (lane & 15);
        aAddr[mt] = sbase + r * 128;
        aSw[mt]   = ((r & 7) << 4);
    }
    #pragma unroll
    for (int ng = 0; ng < 2; ++ng) {
        const int r = warp_n * 32 + ng * 16 + (lane & 7) + ((lane & 16) >> 1);
        bAddr[ng] = sbase + 16384 + r * 128;
        bSw[ng]   = ((r & 7) << 4);
    }

    float acc[4][4][4];
    #pragma unroll
    for (int i = 0; i < 4; ++i)
        #pragma unroll
        for (int j = 0; j < 4; ++j)
            #pragma unroll
            for (int q = 0; q < 4; ++q) acc[i][j][q] = 0.0f;

    const int ntile = K >> 6;

    issue_tile(sbase + sOffA, sbase + sOffB, gA, gB, gStride);
    gA += 64; gB += 64;
    issue_tile(sbase + GSTAGE_BYTES + sOffA, sbase + GSTAGE_BYTES + sOffB, gA, gB, gStride);
    gA += 64; gB += 64;

    uint32_t wOff = 2 * GSTAGE_BYTES, rOff = 0;

    for (int t = 0; t < ntile; ++t) {
        if (t == ntile - 1) { CP_WAIT0(); } else { CP_WAIT1(); }
        __syncthreads();
        if (t + 2 < ntile) {
            issue_tile(sbase + wOff + sOffA, sbase + wOff + sOffB, gA, gB, gStride);
            gA += 64; gB += 64;
            wOff = (wOff == 2 * GSTAGE_BYTES) ? 0u : wOff + GSTAGE_BYTES;
        }

        #pragma unroll
        for (int j = 0; j < 4; ++j) {
            uint32_t a[4][4], b[2][4];
            #pragma unroll
            for (int mt = 0; mt < 4; ++mt)
                LDSM4(a[mt][0], a[mt][1], a[mt][2], a[mt][3],
                      aAddr[mt] + rOff + (((uint32_t)(j * 32) + hiA) ^ aSw[mt]));
            #pragma unroll
            for (int ng = 0; ng < 2; ++ng)
                LDSM4(b[ng][0], b[ng][1], b[ng][2], b[ng][3],
                      bAddr[ng] + rOff + (((uint32_t)(j * 32) + hiB) ^ bSw[ng]));
            #pragma unroll
            for (int mt = 0; mt < 4; ++mt)
                #pragma unroll
                for (int nt = 0; nt < 4; ++nt) {
                    const int ng = nt >> 1;
                    if (nt & 1) MMA16816F16(acc[mt][nt], a[mt][0], a[mt][1], a[mt][2], a[mt][3],
                                            b[ng][2], b[ng][3]);
                    else        MMA16816F16(acc[mt][nt], a[mt][0], a[mt][1], a[mt][2], a[mt][3],
                                            b[ng][0], b[ng][1]);
                }
        }
        __syncthreads();
        rOff = (rOff == 2 * GSTAGE_BYTES) ? 0u : rOff + GSTAGE_BYTES;
    }

    // ---------------- epilogue ----------------
    float* outF; __half* outH; int No; int colL;
    if (fusedUp) {
        if (bn < 32)      { outF = Cf;      outH = nullptr; No = 4096; colL = bn * 128; }
        else if (bn < 34) { outF = nullptr; outH = Ch;      No = 256;  colL = (bn - 32) * 128; }
        else              { outF = nullptr; outH = Ch2;     No = 512;  colL = (bn - 34) * 128; }
    } else { outF = Cf; outH = Ch; No = N; colL = bn * 128; }

    const int row0 = bm * 128 + warp_m * 64 + (lane >> 2);
    const int cw   = warp_n * 32 + (lane & 3) * 2;     // col within CTA tile

    #pragma unroll
    for (int mt = 0; mt < 4; ++mt) {
        #pragma unroll
        for (int nt = 0; nt < 4; ++nt) {
            const int cc = cw + nt * 8;
            const float bz0 = bias[bn * 128 + cc];
            const float bz1 = bias[bn * 128 + cc + 1];
            float v[4];
            v[0] = acc[mt][nt][0] + bz0;
            v[1] = acc[mt][nt][1] + bz1;
            v[2] = acc[mt][nt][2] + bz0;
            v[3] = acc[mt][nt][3] + bz1;
            if (do_gelu) {
                #pragma unroll
                for (int q = 0; q < 4; ++q) v[q] = gelu_exact(v[q]);
            }
            const int gc = colL + cc;
            const size_t r0 = (size_t)(row0 + mt * 16);
            const size_t r1 = r0 + 8;
            if (outF) {
                *reinterpret_cast<float2*>(outF + r0 * No + gc) = make_float2(v[0], v[1]);
                *reinterpret_cast<float2*>(outF + r1 * No + gc) = make_float2(v[2], v[3]);
            }
            if (outH) {
                *reinterpret_cast<__half2*>(outH + r0 * No + gc) =
                    __halves2half2(__float2half_rn(v[0]), __float2half_rn(v[1]));
                *reinterpret_cast<__half2*>(outH + r1 * No + gc) =
                    __halves2half2(__float2half_rn(v[2]), __float2half_rn(v[3]));
            }
        }
    }
}

__global__ void __launch_bounds__(256, 2) gemm_main(
    const __half* __restrict__ A, const __half* __restrict__ B,
    const float* __restrict__ bias,
    float* Cf, __half* Ch, __half* Ch2,
    int N, int K, int do_gelu, int fusedUp)
{
    gemm_body(A, B, bias, Cf, Ch, Ch2, N, K, do_gelu, fusedUp,
              blockIdx.y, blockIdx.x);
}

__global__ void __launch_bounds__(256, 2) gemm_down(
    const __half* __restrict__ A0, const __half* __restrict__ B0,
    const float* __restrict__ bias0, float* C0,
    const __half* __restrict__ A1, const __half* __restrict__ B1,
    const float* __restrict__ bias1, float* C1)
{
    if (blockIdx.z == 0)
        gemm_body(A0, B0, bias0, C0, nullptr, nullptr, HID, 256, 0, 0,
                  blockIdx.y, blockIdx.x);
    else
        gemm_body(A1, B1, bias1, C1, nullptr, nullptr, HID, 512, 0, 0,
                  blockIdx.y, blockIdx.x);
}

// ============================ routed combine ============================
__global__ void __launch_bounds__(256) combine_kernel(
    const float* __restrict__ base, const float* __restrict__ ad0,
    const float* __restrict__ ad1,  const float* __restrict__ xn,
    const float* __restrict__ wm,   const int* __restrict__ idx,
    float* __restrict__ out)
{
    const int t = blockIdx.x;
    const float w  = wm[t];
    const float w1 = 1.0f - w;
    const int id = idx[t];
    const float* asel = (id == 0) ? ad0 : ((id == 1) ? ad1 : xn);
    const int off = t * (HID / 4) + threadIdx.x;
    const float4 b = reinterpret_cast<const float4*>(base)[off];
    const float4 a = reinterpret_cast<const float4*>(asel)[off];
    float4 o;
    o.x = b.x * w + a.x * w1;
    o.y = b.y * w + a.y * w1;
    o.z = b.z * w + a.z * w1;
    o.w = b.w * w + a.w * w1;
    reinterpret_cast<float4*>(out)[off] = o;
}

// ============================ launch ============================
extern "C" void kernel_launch(void* const* d_in, const int* in_sizes, int n_in,
                              void* d_out, int out_size)
{
    const float* x        = (const float*)d_in[0];
    const float* wm       = (const float*)d_in[1];
    const int*   widx     = (const int*)  d_in[2];
    const float* ln_in_g  = (const float*)d_in[3];
    const float* ln_in_b  = (const float*)d_in[4];
    const float* W1       = (const float*)d_in[5];
    const float* b1       = (const float*)d_in[6];
    const float* ln_h_g   = (const float*)d_in[7];
    const float* ln_h_b   = (const float*)d_in[8];
    const float* W2       = (const float*)d_in[9];
    const float* b2       = (const float*)d_in[10];
    const float* a256_w1  = (const float*)d_in[11];
    const float* a256_b1  = (const float*)d_in[12];
    const float* a256_w2  = (const float*)d_in[13];
    const float* a256_b2  = (const float*)d_in[14];
    const float* a512_w1  = (const float*)d_in[15];
    const float* a512_b1  = (const float*)d_in[16];
    const float* a512_w2  = (const float*)d_in[17];
    const float* a512_b2  = (const float*)d_in[18];
    float* out = (float*)d_out;

    cudaFuncSetAttribute(gemm_main, cudaFuncAttributeMaxDynamicSharedMemorySize, GEMM_SMEM);
    cudaFuncSetAttribute(gemm_down, cudaFuncAttributeMaxDynamicSharedMemorySize, GEMM_SMEM);

    float *xnorm, *h, *base, *ad0, *ad1, *bup;
    __half *xnh, *hnh, *t0h, *t1h, *wup, *w2t, *a2t, *b2t;
    cudaGetSymbolAddress((void**)&xnorm, g_xnorm);
    cudaGetSymbolAddress((void**)&h,     g_h);
    cudaGetSymbolAddress((void**)&base,  g_base);
    cudaGetSymbolAddress((void**)&ad0,   g_ad0);
    cudaGetSymbolAddress((void**)&ad1,   g_ad1);
    cudaGetSymbolAddress((void**)&xnh,   g_xnh);
    cudaGetSymbolAddress((void**)&hnh,   g_hnh);
    cudaGetSymbolAddress((void**)&t0h,   g_t0h);
    cudaGetSymbolAddress((void**)&t1h,   g_t1h);
    cudaGetSymbolAddress((void**)&wup,   g_wup);
    cudaGetSymbolAddress((void**)&bup,   g_bup);
    cudaGetSymbolAddress((void**)&w2t,   g_w2t);
    cudaGetSymbolAddress((void**)&a2t,   g_a2t);
    cudaGetSymbolAddress((void**)&b2t,   g_b2t);

    // weight prep
    transpose_big<<<dim3(128, 128, 2), 256>>>(W1, W2, wup, w2t);
    transpose_adapters<<<dim3(32, 32, 4), 256>>>(a256_w1, a256_w2, a512_w1, a512_w2,
                                                 wup, a2t, b2t);
    bias_concat<<<(NUP + 255) / 256, 256>>>(b1, a256_b1, a512_b1, bup);

    // x_norm
    ln_kernel<HID><<<TOKENS, 256>>>(x, ln_in_g, ln_in_b, xnorm, xnh);

    // fused up-projection: [h | t0 | t1] = gelu(x_norm @ [W1|a1|b1] + bias')
    gemm_main<<<dim3(NUP / 128, TOKENS / 128), 256, GEMM_SMEM>>>(
        xnh, wup, bup, h, t0h, t1h, NUP, HID, 1, 1);

    // h_norm
    ln_kernel<FFN><<<TOKENS, 256>>>(h, ln_h_g, ln_h_b, nullptr, hnh);

    // base = h_norm @ W2 + b2
    gemm_main<<<dim3(HID / 128, TOKENS / 128), 256, GEMM_SMEM>>>(
        hnh, w2t, b2, base, nullptr, nullptr, HID, FFN, 0, 0);

    // fused adapter-down: ad0 = t0 @ a2^T + b, ad1 = t1 @ b2^T + b
    gemm_down<<<dim3(HID / 128, TOKENS / 128, 2), 256, GEMM_SMEM>>>(
        t0h, a2t, a256_b2, ad0, t1h, b2t, a512_b2, ad1);

    // combine
    combine_kernel<<<TOKENS, 256>>>(base, ad0, ad1, xnorm, wm, widx, out);
}

// round 7
// speedup vs baseline: 7.9264x; 1.0279x over previous
#include <cuda_runtime.h>
#include <cuda_fp16.h>
#include <math.h>
#include <stdint.h>

#define TOKENS 8192
#define HID    1024
#define FFN    4096
#define NUP    4864      // 4096 + 256 + 512 fused up-projection width

// ============================ scratch (device globals) ============================
__device__ float  g_xnorm[TOKENS * HID];
__device__ __half g_xnh[TOKENS * HID];
__device__ __half g_hh[TOKENS * FFN];          // h = gelu(x_norm@W1+b1), fp16
__device__ float  g_mu[TOKENS], g_inv[TOKENS]; // LN(h) row stats
__device__ float  g_ad0[TOKENS * HID], g_ad1[TOKENS * HID];
__device__ __half g_t0h[TOKENS * 256];
__device__ __half g_t1h[TOKENS * 512];
__device__ __half g_wup[NUP * HID];            // [W1 | a256_w1 | a512_w1]^T  fp16
__device__ float  g_bup[NUP];
__device__ __half g_w2t[HID * FFN];            // (ln_h_g ∘ W2)^T fp16
__device__ __half g_a2t[HID * 256];
__device__ __half g_b2t[HID * 512];
__device__ float  g_c1[HID], g_c2[HID];        // LN-through-GEMM correction vectors
__device__ float  g_p1[16 * HID], g_p2[16 * HID];

__device__ __forceinline__ float gelu_exact(float x) {
    return 0.5f * x * (1.0f + erff(x * 0.7071067811865475f));
}
__device__ __forceinline__ uint32_t smem_u32(const void* p) {
    uint32_t a;
    asm("{ .reg .u64 t; cvta.to.shared.u64 t, %1; cvt.u32.u64 %0, t; }" : "=r"(a) : "l"(p));
    return a;
}

#define CP_ASYNC16(s, g) \
    asm volatile("cp.async.cg.shared.global [%0], [%1], 16;" :: "r"(s), "l"(g))
#define CP_COMMIT() asm volatile("cp.async.commit_group;")
#define CP_WAIT1()  asm volatile("cp.async.wait_group 1;")
#define CP_WAIT0()  asm volatile("cp.async.wait_group 0;")

#define LDSM4(r0, r1, r2, r3, addr) \
    asm volatile("ldmatrix.sync.aligned.m8n8.x4.shared.b16 {%0,%1,%2,%3}, [%4];" \
                 : "=r"(r0), "=r"(r1), "=r"(r2), "=r"(r3) : "r"(addr))

#define MMA16816F16(d, a0, a1, a2, a3, b0, b1) \
    asm volatile("mma.sync.aligned.m16n8k16.row.col.f32.f16.f16.f32 " \
                 "{%0,%1,%2,%3}, {%4,%5,%6,%7}, {%8,%9}, {%0,%1,%2,%3};" \
                 : "+f"((d)[0]), "+f"((d)[1]), "+f"((d)[2]), "+f"((d)[3]) \
                 : "r"(a0), "r"(a1), "r"(a2), "r"(a3), "r"(b0), "r"(b1))

// ============================ transpose to fp16 W^T (scale optional) ============================
__device__ __forceinline__ void do_transpose(
    const float* __restrict__ W, int K, int N, __half* __restrict__ T, int rowOff,
    const float* __restrict__ scale)
{
    __shared__ float s[32][33];
    const int n0 = blockIdx.x * 32, k0 = blockIdx.y * 32;
    if (n0 >= N || k0 >= K) return;
    const int tr = threadIdx.x >> 3;
    const int tc = (threadIdx.x & 7) * 4;
    const float4 v = *reinterpret_cast<const float4*>(W + (size_t)(k0 + tr) * N + n0 + tc);
    s[tr][tc + 0] = v.x; s[tr][tc + 1] = v.y; s[tr][tc + 2] = v.z; s[tr][tc + 3] = v.w;
    __syncthreads();
    const size_t off = (size_t)(rowOff + n0 + tr) * K + k0 + tc;
    #pragma unroll
    for (int q = 0; q < 2; ++q) {
        float x0 = s[tc + q * 2 + 0][tr];
        float x1 = s[tc + q * 2 + 1][tr];
        if (scale) {
            x0 *= scale[k0 + tc + q * 2 + 0];
            x1 *= scale[k0 + tc + q * 2 + 1];
        }
        *reinterpret_cast<__half2*>(T + off + q * 2) =
            __halves2half2(__float2half_rn(x0), __float2half_rn(x1));
    }
}

__global__ void __launch_bounds__(256) transpose_big(
    const float* __restrict__ W1, const float* __restrict__ W2,
    const float* __restrict__ lnhg, __half* wup, __half* w2t)
{
    if (blockIdx.z == 0) do_transpose(W1, HID, FFN, wup, 0, nullptr);
    else                 do_transpose(W2, FFN, HID, w2t, 0, lnhg);
}

__global__ void __launch_bounds__(256) transpose_adapters(
    const float* __restrict__ aw1, const float* __restrict__ aw2,
    const float* __restrict__ bw1, const float* __restrict__ bw2,
    __half* wup, __half* a2t, __half* b2t)
{
    switch (blockIdx.z) {
        case 0: do_transpose(aw1, HID, 256, wup, 4096, nullptr); break;
        case 1: do_transpose(aw2, 256, HID, a2t, 0, nullptr);    break;
        case 2: do_transpose(bw1, HID, 512, wup, 4352, nullptr); break;
        default: do_transpose(bw2, 512, HID, b2t, 0, nullptr);   break;
    }
}

__global__ void __launch_bounds__(256) bias_concat(
    const float* __restrict__ b1, const float* __restrict__ ab1,
    const float* __restrict__ bb1, float* __restrict__ out)
{
    const int i = blockIdx.x * 256 + threadIdx.x;
    if (i >= NUP) return;
    float v;
    if (i < 4096) v = b1[i];
    else if (i < 4352) v = ab1[i - 4096];
    else v = bb1[i - 4352];
    out[i] = v;
}

// c1[n] = sum_f g[f]*W2[f,n];  c2[n] = sum_f b[f]*W2[f,n] + b2[n]
__global__ void __launch_bounds__(128) colsum_partial(
    const float* __restrict__ W2, const float* __restrict__ g,
    const float* __restrict__ b, float* __restrict__ p1, float* __restrict__ p2)
{
    const int n = blockIdx.x * 128 + threadIdx.x;
    const int f0 = blockIdx.y * 256;
    float s1 = 0.0f, s2 = 0.0f;
    #pragma unroll 4
    for (int f = f0; f < f0 + 256; ++f) {
        const float w = W2[(size_t)f * HID + n];
        s1 += g[f] * w;
        s2 += b[f] * w;
    }
    p1[blockIdx.y * HID + n] = s1;
    p2[blockIdx.y * HID + n] = s2;
}

__global__ void __launch_bounds__(256) colsum_reduce(
    const float* __restrict__ p1, const float* __restrict__ p2,
    const float* __restrict__ b2, float* __restrict__ c1, float* __restrict__ c2)
{
    const int n = blockIdx.x * 256 + threadIdx.x;
    float s1 = 0.0f, s2 = 0.0f;
    #pragma unroll
    for (int q = 0; q < 16; ++q) { s1 += p1[q * HID + n]; s2 += p2[q * HID + n]; }
    c1[n] = s1;
    c2[n] = s2 + b2[n];
}

// ============================ reductions / LN ============================
__device__ __forceinline__ void block_reduce_sum2(float& s, float& ss) {
    #pragma unroll
    for (int off = 16; off > 0; off >>= 1) {
        s  += __shfl_down_sync(0xffffffffu, s, off);
        ss += __shfl_down_sync(0xffffffffu, ss, off);
    }
    __shared__ float sh_s[8], sh_ss[8];
    int warp = threadIdx.x >> 5, lane = threadIdx.x & 31;
    if (lane == 0) { sh_s[warp] = s; sh_ss[warp] = ss; }
    __syncthreads();
    if (warp == 0) {
        s  = (lane < 8) ? sh_s[lane]  : 0.0f;
        ss = (lane < 8) ? sh_ss[lane] : 0.0f;
        #pragma unroll
        for (int off = 4; off > 0; off >>= 1) {
            s  += __shfl_down_sync(0xffffffffu, s, off);
            ss += __shfl_down_sync(0xffffffffu, ss, off);
        }
        if (lane == 0) { sh_s[0] = s; sh_ss[0] = ss; }
    }
    __syncthreads();
    s = sh_s[0]; ss = sh_ss[0];
}

__global__ void __launch_bounds__(256) ln1024_kernel(
    const float* __restrict__ in, const float* __restrict__ gw,
    const float* __restrict__ bw, float* __restrict__ outf,
    __half* __restrict__ oh)
{
    const size_t row = blockIdx.x;
    const float4* inr = reinterpret_cast<const float4*>(in) + row * 256;
    const float4 v = inr[threadIdx.x];
    float s  = v.x + v.y + v.z + v.w;
    float ss = v.x * v.x + v.y * v.y + v.z * v.z + v.w * v.w;
    block_reduce_sum2(s, ss);
    const float mu  = s * (1.0f / HID);
    const float var = ss * (1.0f / HID) - mu * mu;
    const float inv = rsqrtf(var + 1e-5f);

    const int c = threadIdx.x;
    const float4 gv = reinterpret_cast<const float4*>(gw)[c];
    const float4 bv = reinterpret_cast<const float4*>(bw)[c];
    float4 o;
    o.x = (v.x - mu) * inv * gv.x + bv.x;
    o.y = (v.y - mu) * inv * gv.y + bv.y;
    o.z = (v.z - mu) * inv * gv.z + bv.z;
    o.w = (v.w - mu) * inv * gv.w + bv.w;
    reinterpret_cast<float4*>(outf)[row * 256 + c] = o;
    __half2* ohr = reinterpret_cast<__half2*>(oh) + row * 512;
    ohr[c * 2 + 0] = __halves2half2(__float2half_rn(o.x), __float2half_rn(o.y));
    ohr[c * 2 + 1] = __halves2half2(__float2half_rn(o.z), __float2half_rn(o.w));
}

// per-row mean/inv-std of h (fp16, width 4096)
__global__ void __launch_bounds__(256) rowstat_kernel(
    const __half* __restrict__ hh, float* __restrict__ mu, float* __restrict__ inv)
{
    const size_t row = blockIdx.x;
    const __half2* hr = reinterpret_cast<const __half2*>(hh) + row * (FFN / 2);
    float s = 0.0f, ss = 0.0f;
    #pragma unroll
    for (int i = 0; i < 8; ++i) {
        const float2 f = __half22float2(hr[threadIdx.x + i * 256]);
        s  += f.x + f.y;
        ss += f.x * f.x + f.y * f.y;
    }
    block_reduce_sum2(s, ss);
    if (threadIdx.x == 0) {
        const float m = s * (1.0f / FFN);
        mu[row]  = m;
        inv[row] = rsqrtf(ss * (1.0f / FFN) - m * m + 1e-5f);
    }
}

// ============================ fp16 mma.sync GEMM mainloop ============================
#define GSTAGES 3
#define GSTAGE_BYTES 32768
#define GEMM_SMEM (GSTAGES * GSTAGE_BYTES)

__device__ __forceinline__ void issue_tile(
    uint32_t dstA, uint32_t dstB,
    const __half* gA, const __half* gB, size_t gStride)
{
    #pragma unroll
    for (int p = 0; p < 4; ++p)
        CP_ASYNC16(dstA + p * 4096, gA + p * gStride);
    #pragma unroll
    for (int p = 0; p < 4; ++p)
        CP_ASYNC16(dstB + p * 4096, gB + p * gStride);
    CP_COMMIT();
}

__device__ __forceinline__ void gemm_mainloop(
    const __half* __restrict__ A, const __half* __restrict__ B,
    int K, int bm, int bn, float (&acc)[4][4][4])
{
    extern __shared__ char smem[];
    const uint32_t sbase = smem_u32(smem);
    const int tid = threadIdx.x, lane = tid & 31, wid = tid >> 5;
    const int warp_m = wid & 1, warp_n = wid >> 1;

    const int lrow = tid >> 3;
    const int lch  = tid & 7;
    const uint32_t sOffA = (uint32_t)lrow * 128 + ((lch ^ (lrow & 7)) << 4);
    const uint32_t sOffB = sOffA + 16384;
    const __half* gA = A + (size_t)(bm * 128 + lrow) * K + lch * 8;
    const __half* gB = B + (size_t)(bn * 128 + lrow) * K + lch * 8;
    const size_t gStride = (size_t)32 * K;

    uint32_t aAddr[4], bAddr[2], aSw[4], bSw[2];
    const uint32_t hiA = (lane & 16);
    const uint32_t hiB = ((lane & 8) << 1);
    #pragma unroll
    for (int mt = 0; mt < 4; ++mt) {
        const int r = warp_m * 64 + mt * 16 + (lane & 15);
        aAddr[mt] = sbase + r * 128;
        aSw[mt]   = ((r & 7) << 4);
    }
    #pragma unroll
    for (int ng = 0; ng < 2; ++ng) {
        const int r = warp_n * 32 + ng * 16 + (lane & 7) + ((lane & 16) >> 1);
        bAddr[ng] = sbase + 16384 + r * 128;
        bSw[ng]   = ((r & 7) << 4);
    }

    #pragma unroll
    for (int i = 0; i < 4; ++i)
        #pragma unroll
        for (int j = 0; j < 4; ++j)
            #pragma unroll
            for (int q = 0; q < 4; ++q) acc[i][j][q] = 0.0f;

    const int ntile = K >> 6;

    issue_tile(sbase + sOffA, sbase + sOffB, gA, gB, gStride);
    gA += 64; gB += 64;
    issue_tile(sbase + GSTAGE_BYTES + sOffA, sbase + GSTAGE_BYTES + sOffB, gA, gB, gStride);
    gA += 64; gB += 64;

    uint32_t wOff = 2 * GSTAGE_BYTES, rOff = 0;

    for (int t = 0; t < ntile; ++t) {
        if (t == ntile - 1) { CP_WAIT0(); } else { CP_WAIT1(); }
        __syncthreads();
        if (t + 2 < ntile) {
            issue_tile(sbase + wOff + sOffA, sbase + wOff + sOffB, gA, gB, gStride);
            gA += 64; gB += 64;
            wOff = (wOff == 2 * GSTAGE_BYTES) ? 0u : wOff + GSTAGE_BYTES;
        }

        #pragma unroll
        for (int j = 0; j < 4; ++j) {
            uint32_t a[4][4], b[2][4];
            #pragma unroll
            for (int mt = 0; mt < 4; ++mt)
                LDSM4(a[mt][0], a[mt][1], a[mt][2], a[mt][3],
                      aAddr[mt] + rOff + (((uint32_t)(j * 32) + hiA) ^ aSw[mt]));
            #pragma unroll
            for (int ng = 0; ng < 2; ++ng)
                LDSM4(b[ng][0], b[ng][1], b[ng][2], b[ng][3],
                      bAddr[ng] + rOff + (((uint32_t)(j * 32) + hiB) ^ bSw[ng]));
            #pragma unroll
            for (int mt = 0; mt < 4; ++mt)
                #pragma unroll
                for (int nt = 0; nt < 4; ++nt) {
                    const int ng = nt >> 1;
                    if (nt & 1) MMA16816F16(acc[mt][nt], a[mt][0], a[mt][1], a[mt][2], a[mt][3],
                                            b[ng][2], b[ng][3]);
                    else        MMA16816F16(acc[mt][nt], a[mt][0], a[mt][1], a[mt][2], a[mt][3],
                                            b[ng][0], b[ng][1]);
                }
        }
        __syncthreads();
        rOff = (rOff == 2 * GSTAGE_BYTES) ? 0u : rOff + GSTAGE_BYTES;
    }
}

// ---- fused up-projection: [h | t0 | t1] = gelu(x_norm @ [W1|a1|b1] + bias'), fp16 out ----
__global__ void __launch_bounds__(256, 2) gemm_up(
    const __half* __restrict__ A, const __half* __restrict__ B,
    const float* __restrict__ bias,
    __half* __restrict__ Hh, __half* __restrict__ T0, __half* __restrict__ T1)
{
    float acc[4][4][4];
    const int bm = blockIdx.y, bn = blockIdx.x;
    gemm_mainloop(A, B, HID, bm, bn, acc);

    __half* outH; int No; int colL;
    if (bn < 32)      { outH = Hh; No = 4096; colL = bn * 128; }
    else if (bn < 34) { outH = T0; No = 256;  colL = (bn - 32) * 128; }
    else              { outH = T1; No = 512;  colL = (bn - 34) * 128; }

    const int lane = threadIdx.x & 31, wid = threadIdx.x >> 5;
    const int warp_m = wid & 1, warp_n = wid >> 1;
    const int row0 = bm * 128 + warp_m * 64 + (lane >> 2);
    const int cw   = warp_n * 32 + (lane & 3) * 2;

    #pragma unroll
    for (int mt = 0; mt < 4; ++mt) {
        #pragma unroll
        for (int nt = 0; nt < 4; ++nt) {
            const int cc = cw + nt * 8;
            const float bz0 = bias[bn * 128 + cc];
            const float bz1 = bias[bn * 128 + cc + 1];
            float v[4];
            v[0] = gelu_exact(acc[mt][nt][0] + bz0);
            v[1] = gelu_exact(acc[mt][nt][1] + bz1);
            v[2] = gelu_exact(acc[mt][nt][2] + bz0);
            v[3] = gelu_exact(acc[mt][nt][3] + bz1);
            const int gc = colL + cc;
            const size_t r0 = (size_t)(row0 + mt * 16);
            const size_t r1 = r0 + 8;
            *reinterpret_cast<__half2*>(outH + r0 * No + gc) =
                __halves2half2(__float2half_rn(v[0]), __float2half_rn(v[1]));
            *reinterpret_cast<__half2*>(outH + r1 * No + gc) =
                __halves2half2(__float2half_rn(v[2]), __float2half_rn(v[3]));
        }
    }
}

// ---- fused adapter-down: ad = t @ a2^T + bias, fp32 out ----
__global__ void __launch_bounds__(256, 2) gemm_down(
    const __half* __restrict__ A0, const __half* __restrict__ B0,
    const float* __restrict__ bias0, float* __restrict__ C0,
    const __half* __restrict__ A1, const __half* __restrict__ B1,
    const float* __restrict__ bias1, float* __restrict__ C1)
{
    float acc[4][4][4];
    const int bm = blockIdx.y, bn = blockIdx.x;
    const __half* A; const __half* B; const float* bias; float* C; int K;
    if (blockIdx.z == 0) { A = A0; B = B0; bias = bias0; C = C0; K = 256; }
    else                 { A = A1; B = B1; bias = bias1; C = C1; K = 512; }
    gemm_mainloop(A, B, K, bm, bn, acc);

    const int lane = threadIdx.x & 31, wid = threadIdx.x >> 5;
    const int warp_m = wid & 1, warp_n = wid >> 1;
    const int row0 = bm * 128 + warp_m * 64 + (lane >> 2);
    const int cw   = warp_n * 32 + (lane & 3) * 2;

    #pragma unroll
    for (int mt = 0; mt < 4; ++mt) {
        #pragma unroll
        for (int nt = 0; nt < 4; ++nt) {
            const int cc = cw + nt * 8;
            const int gc = bn * 128 + cc;
            const float bz0 = bias[gc], bz1 = bias[gc + 1];
            const size_t r0 = (size_t)(row0 + mt * 16);
            const size_t r1 = r0 + 8;
            *reinterpret_cast<float2*>(C + r0 * HID + gc) =
                make_float2(acc[mt][nt][0] + bz0, acc[mt][nt][1] + bz1);
            *reinterpret_cast<float2*>(C + r1 * HID + gc) =
                make_float2(acc[mt][nt][2] + bz0, acc[mt][nt][3] + bz1);
        }
    }
}

// ---- final: out = (inv_r*(h@(g∘W2) − mu_r*c1) + c2)*w_r + asel*(1−w_r) ----
__global__ void __launch_bounds__(256, 2) gemm_final(
    const __half* __restrict__ A, const __half* __restrict__ B,
    const float* __restrict__ c1, const float* __restrict__ c2,
    const float* __restrict__ mu, const float* __restrict__ inv,
    const float* __restrict__ wm, const int* __restrict__ idx,
    const float* __restrict__ ad0, const float* __restrict__ ad1,
    const float* __restrict__ xn, float* __restrict__ out)
{
    float acc[4][4][4];
    const int bm = blockIdx.y, bn = blockIdx.x;
    gemm_mainloop(A, B, FFN, bm, bn, acc);

    const int lane = threadIdx.x & 31, wid = threadIdx.x >> 5;
    const int warp_m = wid & 1, warp_n = wid >> 1;
    const int row0 = bm * 128 + warp_m * 64 + (lane >> 2);
    const int cw   = warp_n * 32 + (lane & 3) * 2;

    #pragma unroll
    for (int mt = 0; mt < 4; ++mt) {
        #pragma unroll
        for (int rr = 0; rr < 2; ++rr) {
            const int r = row0 + mt * 16 + rr * 8;
            const float muv = mu[r], invv = inv[r];
            const float w = wm[r], w1 = 1.0f - w;
            const int id = idx[r];
            const float* asel = (id == 0) ? ad0 : ((id == 1) ? ad1 : xn);
            #pragma unroll
            for (int nt = 0; nt < 4; ++nt) {
                const int gc = bn * 128 + cw + nt * 8;
                const float v0 = invv * (acc[mt][nt][rr * 2 + 0] - muv * c1[gc])     + c2[gc];
                const float v1 = invv * (acc[mt][nt][rr * 2 + 1] - muv * c1[gc + 1]) + c2[gc + 1];
                const float2 a = *reinterpret_cast<const float2*>(asel + (size_t)r * HID + gc);
                *reinterpret_cast<float2*>(out + (size_t)r * HID + gc) =
                    make_float2(v0 * w + a.x * w1, v1 * w + a.y * w1);
            }
        }
    }
}

// ============================ launch ============================
extern "C" void kernel_launch(void* const* d_in, const int* in_sizes, int n_in,
                              void* d_out, int out_size)
{
    const float* x        = (const float*)d_in[0];
    const float* wm       = (const float*)d_in[1];
    const int*   widx     = (const int*)  d_in[2];
    const float* ln_in_g  = (const float*)d_in[3];
    const float* ln_in_b  = (const float*)d_in[4];
    const float* W1       = (const float*)d_in[5];
    const float* b1       = (const float*)d_in[6];
    const float* ln_h_g   = (const float*)d_in[7];
    const float* ln_h_b   = (const float*)d_in[8];
    const float* W2       = (const float*)d_in[9];
    const float* b2       = (const float*)d_in[10];
    const float* a256_w1  = (const float*)d_in[11];
    const float* a256_b1  = (const float*)d_in[12];
    const float* a256_w2  = (const float*)d_in[13];
    const float* a256_b2  = (const float*)d_in[14];
    const float* a512_w1  = (const float*)d_in[15];
    const float* a512_b1  = (const float*)d_in[16];
    const float* a512_w2  = (const float*)d_in[17];
    const float* a512_b2  = (const float*)d_in[18];
    float* out = (float*)d_out;

    cudaFuncSetAttribute(gemm_up,    cudaFuncAttributeMaxDynamicSharedMemorySize, GEMM_SMEM);
    cudaFuncSetAttribute(gemm_down,  cudaFuncAttributeMaxDynamicSharedMemorySize, GEMM_SMEM);
    cudaFuncSetAttribute(gemm_final, cudaFuncAttributeMaxDynamicSharedMemorySize, GEMM_SMEM);

    float *xnorm, *ad0, *ad1, *bup, *mu, *inv, *c1, *c2, *p1, *p2;
    __half *xnh, *hh, *t0h, *t1h, *wup, *w2t, *a2t, *b2t;
    cudaGetSymbolAddress((void**)&xnorm, g_xnorm);
    cudaGetSymbolAddress((void**)&ad0,   g_ad0);
    cudaGetSymbolAddress((void**)&ad1,   g_ad1);
    cudaGetSymbolAddress((void**)&bup,   g_bup);
    cudaGetSymbolAddress((void**)&mu,    g_mu);
    cudaGetSymbolAddress((void**)&inv,   g_inv);
    cudaGetSymbolAddress((void**)&c1,    g_c1);
    cudaGetSymbolAddress((void**)&c2,    g_c2);
    cudaGetSymbolAddress((void**)&p1,    g_p1);
    cudaGetSymbolAddress((void**)&p2,    g_p2);
    cudaGetSymbolAddress((void**)&xnh,   g_xnh);
    cudaGetSymbolAddress((void**)&hh,    g_hh);
    cudaGetSymbolAddress((void**)&t0h,   g_t0h);
    cudaGetSymbolAddress((void**)&t1h,   g_t1h);
    cudaGetSymbolAddress((void**)&wup,   g_wup);
    cudaGetSymbolAddress((void**)&w2t,   g_w2t);
    cudaGetSymbolAddress((void**)&a2t,   g_a2t);
    cudaGetSymbolAddress((void**)&b2t,   g_b2t);

    // weight prep
    transpose_big<<<dim3(128, 128, 2), 256>>>(W1, W2, ln_h_g, wup, w2t);
    transpose_adapters<<<dim3(32, 32, 4), 256>>>(a256_w1, a256_w2, a512_w1, a512_w2,
                                                 wup, a2t, b2t);
    bias_concat<<<(NUP + 255) / 256, 256>>>(b1, a256_b1, a512_b1, bup);
    colsum_partial<<<dim3(HID / 128, 16), 128>>>(W2, ln_h_g, ln_h_b, p1, p2);
    colsum_reduce<<<HID / 256, 256>>>(p1, p2, b2, c1, c2);

    // x_norm
    ln1024_kernel<<<TOKENS, 256>>>(x, ln_in_g, ln_in_b, xnorm, xnh);

    // fused up-projection (h, t0, t1 all fp16)
    gemm_up<<<dim3(NUP / 128, TOKENS / 128), 256, GEMM_SMEM>>>(
        xnh, wup, bup, hh, t0h, t1h);

    // row stats of h (replaces LN pass)
    rowstat_kernel<<<TOKENS, 256>>>(hh, mu, inv);

    // adapter-down projections
    gemm_down<<<dim3(HID / 128, TOKENS / 128, 2), 256, GEMM_SMEM>>>(
        t0h, a2t, a256_b2, ad0, t1h, b2t, a512_b2, ad1);

    // final GEMM with LN-correction + routed combine fused in epilogue
    gemm_final<<<dim3(HID / 128, TOKENS / 128), 256, GEMM_SMEM>>>(
        hh, w2t, c1, c2, mu, inv, wm, widx, ad0, ad1, xnorm, out);
}

// round 8
// speedup vs baseline: 7.9758x; 1.0062x over previous
#include <cuda_runtime.h>
#include <cuda_fp16.h>
#include <math.h>
#include <stdint.h>

#define TOKENS 8192
#define HID    1024
#define FFN    4096
#define NUP    4864      // 4096 + 256 + 512 fused up-projection width

// ============================ scratch (device globals) ============================
__device__ __half g_xnh[TOKENS * HID];
__device__ __half g_hh[TOKENS * FFN];          // h = gelu(x_norm@W1+b1), fp16
__device__ float  g_mu[TOKENS], g_inv[TOKENS]; // LN(h) row stats
__device__ float  g_ad0[TOKENS * HID], g_ad1[TOKENS * HID];
__device__ __half g_t0h[TOKENS * 256];
__device__ __half g_t1h[TOKENS * 512];
__device__ __half g_wup[NUP * HID];            // [W1 | a256_w1 | a512_w1]^T  fp16
__device__ float  g_bup[NUP];
__device__ __half g_w2t[HID * FFN];            // (ln_h_g ∘ W2)^T fp16
__device__ __half g_a2t[HID * 256];
__device__ __half g_b2t[HID * 512];
__device__ float  g_c1[HID], g_c2[HID];        // LN-through-GEMM correction vectors
__device__ float  g_p1[64 * HID], g_p2[64 * HID];

__device__ __forceinline__ float gelu_exact(float x) {
    return 0.5f * x * (1.0f + erff(x * 0.7071067811865475f));
}
__device__ __forceinline__ uint32_t smem_u32(const void* p) {
    uint32_t a;
    asm("{ .reg .u64 t; cvta.to.shared.u64 t, %1; cvt.u32.u64 %0, t; }" : "=r"(a) : "l"(p));
    return a;
}

#define CP_ASYNC16(s, g) \
    asm volatile("cp.async.cg.shared.global [%0], [%1], 16;" :: "r"(s), "l"(g))
#define CP_COMMIT() asm volatile("cp.async.commit_group;")
#define CP_WAIT1()  asm volatile("cp.async.wait_group 1;")
#define CP_WAIT0()  asm volatile("cp.async.wait_group 0;")

#define LDSM4(r0, r1, r2, r3, addr) \
    asm volatile("ldmatrix.sync.aligned.m8n8.x4.shared.b16 {%0,%1,%2,%3}, [%4];" \
                 : "=r"(r0), "=r"(r1), "=r"(r2), "=r"(r3) : "r"(addr))

#define MMA16816F16(d, a0, a1, a2, a3, b0, b1) \
    asm volatile("mma.sync.aligned.m16n8k16.row.col.f32.f16.f16.f32 " \
                 "{%0,%1,%2,%3}, {%4,%5,%6,%7}, {%8,%9}, {%0,%1,%2,%3};" \
                 : "+f"((d)[0]), "+f"((d)[1]), "+f"((d)[2]), "+f"((d)[3]) \
                 : "r"(a0), "r"(a1), "r"(a2), "r"(a3), "r"(b0), "r"(b1))

// ============================ transpose to fp16 W^T (scale optional) ============================
__device__ __forceinline__ void do_transpose(
    const float* __restrict__ W, int K, int N, __half* __restrict__ T, int rowOff,
    const float* __restrict__ scale)
{
    __shared__ float s[32][33];
    const int n0 = blockIdx.x * 32, k0 = blockIdx.y * 32;
    if (n0 >= N || k0 >= K) return;
    const int tr = threadIdx.x >> 3;
    const int tc = (threadIdx.x & 7) * 4;
    const float4 v = *reinterpret_cast<const float4*>(W + (size_t)(k0 + tr) * N + n0 + tc);
    s[tr][tc + 0] = v.x; s[tr][tc + 1] = v.y; s[tr][tc + 2] = v.z; s[tr][tc + 3] = v.w;
    __syncthreads();
    const size_t off = (size_t)(rowOff + n0 + tr) * K + k0 + tc;
    #pragma unroll
    for (int q = 0; q < 2; ++q) {
        float x0 = s[tc + q * 2 + 0][tr];
        float x1 = s[tc + q * 2 + 1][tr];
        if (scale) {
            x0 *= scale[k0 + tc + q * 2 + 0];
            x1 *= scale[k0 + tc + q * 2 + 1];
        }
        *reinterpret_cast<__half2*>(T + off + q * 2) =
            __halves2half2(__float2half_rn(x0), __float2half_rn(x1));
    }
}

__global__ void __launch_bounds__(256) transpose_big(
    const float* __restrict__ W1, const float* __restrict__ W2,
    const float* __restrict__ lnhg, __half* wup, __half* w2t)
{
    if (blockIdx.z == 0) do_transpose(W1, HID, FFN, wup, 0, nullptr);
    else                 do_transpose(W2, FFN, HID, w2t, 0, lnhg);
}

__global__ void __launch_bounds__(256) transpose_adapters(
    const float* __restrict__ aw1, const float* __restrict__ aw2,
    const float* __restrict__ bw1, const float* __restrict__ bw2,
    __half* wup, __half* a2t, __half* b2t)
{
    switch (blockIdx.z) {
        case 0: do_transpose(aw1, HID, 256, wup, 4096, nullptr); break;
        case 1: do_transpose(aw2, 256, HID, a2t, 0, nullptr);    break;
        case 2: do_transpose(bw1, HID, 512, wup, 4352, nullptr); break;
        default: do_transpose(bw2, 512, HID, b2t, 0, nullptr);   break;
    }
}

__global__ void __launch_bounds__(256) bias_concat(
    const float* __restrict__ b1, const float* __restrict__ ab1,
    const float* __restrict__ bb1, float* __restrict__ out)
{
    const int i = blockIdx.x * 256 + threadIdx.x;
    if (i >= NUP) return;
    float v;
    if (i < 4096) v = b1[i];
    else if (i < 4352) v = ab1[i - 4096];
    else v = bb1[i - 4352];
    out[i] = v;
}

// c1[n] = sum_f g[f]*W2[f,n];  c2[n] = sum_f b[f]*W2[f,n] + b2[n]
__global__ void __launch_bounds__(128) colsum_partial(
    const float* __restrict__ W2, const float* __restrict__ g,
    const float* __restrict__ b, float* __restrict__ p1, float* __restrict__ p2)
{
    const int n = blockIdx.x * 128 + threadIdx.x;     // 8 blocks in x
    const int f0 = blockIdx.y * 64;                   // 64 blocks in y
    float s1 = 0.0f, s2 = 0.0f;
    #pragma unroll 8
    for (int f = f0; f < f0 + 64; ++f) {
        const float w = W2[(size_t)f * HID + n];
        s1 += g[f] * w;
        s2 += b[f] * w;
    }
    p1[blockIdx.y * HID + n] = s1;
    p2[blockIdx.y * HID + n] = s2;
}

__global__ void __launch_bounds__(256) colsum_reduce(
    const float* __restrict__ p1, const float* __restrict__ p2,
    const float* __restrict__ b2, float* __restrict__ c1, float* __restrict__ c2)
{
    const int n = blockIdx.x * 256 + threadIdx.x;
    float s1 = 0.0f, s2 = 0.0f;
    #pragma unroll
    for (int q = 0; q < 64; ++q) { s1 += p1[q * HID + n]; s2 += p2[q * HID + n]; }
    c1[n] = s1;
    c2[n] = s2 + b2[n];
}

// ============================ reductions / LN ============================
__device__ __forceinline__ void block_reduce_sum2(float& s, float& ss) {
    #pragma unroll
    for (int off = 16; off > 0; off >>= 1) {
        s  += __shfl_down_sync(0xffffffffu, s, off);
        ss += __shfl_down_sync(0xffffffffu, ss, off);
    }
    __shared__ float sh_s[8], sh_ss[8];
    int warp = threadIdx.x >> 5, lane = threadIdx.x & 31;
    if (lane == 0) { sh_s[warp] = s; sh_ss[warp] = ss; }
    __syncthreads();
    if (warp == 0) {
        s  = (lane < 8) ? sh_s[lane]  : 0.0f;
        ss = (lane < 8) ? sh_ss[lane] : 0.0f;
        #pragma unroll
        for (int off = 4; off > 0; off >>= 1) {
            s  += __shfl_down_sync(0xffffffffu, s, off);
            ss += __shfl_down_sync(0xffffffffu, ss, off);
        }
        if (lane == 0) { sh_s[0] = s; sh_ss[0] = ss; }
    }
    __syncthreads();
    s = sh_s[0]; ss = sh_ss[0];
}

__global__ void __launch_bounds__(256) ln1024_kernel(
    const float* __restrict__ in, const float* __restrict__ gw,
    const float* __restrict__ bw, __half* __restrict__ oh)
{
    const size_t row = blockIdx.x;
    const float4* inr = reinterpret_cast<const float4*>(in) + row * 256;
    const float4 v = inr[threadIdx.x];
    float s  = v.x + v.y + v.z + v.w;
    float ss = v.x * v.x + v.y * v.y + v.z * v.z + v.w * v.w;
    block_reduce_sum2(s, ss);
    const float mu  = s * (1.0f / HID);
    const float var = ss * (1.0f / HID) - mu * mu;
    const float inv = rsqrtf(var + 1e-5f);

    const int c = threadIdx.x;
    const float4 gv = reinterpret_cast<const float4*>(gw)[c];
    const float4 bv = reinterpret_cast<const float4*>(bw)[c];
    float4 o;
    o.x = (v.x - mu) * inv * gv.x + bv.x;
    o.y = (v.y - mu) * inv * gv.y + bv.y;
    o.z = (v.z - mu) * inv * gv.z + bv.z;
    o.w = (v.w - mu) * inv * gv.w + bv.w;
    __half2* ohr = reinterpret_cast<__half2*>(oh) + row * 512;
    ohr[c * 2 + 0] = __halves2half2(__float2half_rn(o.x), __float2half_rn(o.y));
    ohr[c * 2 + 1] = __halves2half2(__float2half_rn(o.z), __float2half_rn(o.w));
}

// per-row mean/inv-std of h (fp16, width 4096)
__global__ void __launch_bounds__(256) rowstat_kernel(
    const __half* __restrict__ hh, float* __restrict__ mu, float* __restrict__ inv)
{
    const size_t row = blockIdx.x;
    const __half2* hr = reinterpret_cast<const __half2*>(hh) + row * (FFN / 2);
    float s = 0.0f, ss = 0.0f;
    #pragma unroll
    for (int i = 0; i < 8; ++i) {
        const float2 f = __half22float2(hr[threadIdx.x + i * 256]);
        s  += f.x + f.y;
        ss += f.x * f.x + f.y * f.y;
    }
    block_reduce_sum2(s, ss);
    if (threadIdx.x == 0) {
        const float m = s * (1.0f / FFN);
        mu[row]  = m;
        inv[row] = rsqrtf(ss * (1.0f / FFN) - m * m + 1e-5f);
    }
}

// ============================ fp16 mma.sync GEMM mainloop ============================
#define GSTAGES 3
#define GSTAGE_BYTES 32768
#define GEMM_SMEM (GSTAGES * GSTAGE_BYTES)

__device__ __forceinline__ void issue_tile(
    uint32_t dstA, uint32_t dstB,
    const __half* gA, const __half* gB, size_t gStride)
{
    #pragma unroll
    for (int p = 0; p < 4; ++p)
        CP_ASYNC16(dstA + p * 4096, gA + p * gStride);
    #pragma unroll
    for (int p = 0; p < 4; ++p)
        CP_ASYNC16(dstB + p * 4096, gB + p * gStride);
    CP_COMMIT();
}

__device__ __forceinline__ void gemm_mainloop(
    const __half* __restrict__ A, const __half* __restrict__ B,
    int K, int bm, int bn, float (&acc)[4][4][4])
{
    extern __shared__ char smem[];
    const uint32_t sbase = smem_u32(smem);
    const int tid = threadIdx.x, lane = tid & 31, wid = tid >> 5;
    const int warp_m = wid & 1, warp_n = wid >> 1;

    const int lrow = tid >> 3;
    const int lch  = tid & 7;
    const uint32_t sOffA = (uint32_t)lrow * 128 + ((lch ^ (lrow & 7)) << 4);
    const uint32_t sOffB = sOffA + 16384;
    const __half* gA = A + (size_t)(bm * 128 + lrow) * K + lch * 8;
    const __half* gB = B + (size_t)(bn * 128 + lrow) * K + lch * 8;
    const size_t gStride = (size_t)32 * K;

    uint32_t aAddr[4], bAddr[2], aSw[4], bSw[2];
    const uint32_t hiA = (lane & 16);
    const uint32_t hiB = ((lane & 8) << 1);
    #pragma unroll
    for (int mt = 0; mt < 4; ++mt) {
        const int r = warp_m * 64 + mt * 16 + (lane & 15);
        aAddr[mt] = sbase + r * 128;
        aSw[mt]   = ((r & 7) << 4);
    }
    #pragma unroll
    for (int ng = 0; ng < 2; ++ng) {
        const int r = warp_n * 32 + ng * 16 + (lane & 7) + ((lane & 16) >> 1);
        bAddr[ng] = sbase + 16384 + r * 128;
        bSw[ng]   = ((r & 7) << 4);
    }

    #pragma unroll
    for (int i = 0; i < 4; ++i)
        #pragma unroll
        for (int j = 0; j < 4; ++j)
            #pragma unroll
            for (int q = 0; q < 4; ++q) acc[i][j][q] = 0.0f;

    const int ntile = K >> 6;

    issue_tile(sbase + sOffA, sbase + sOffB, gA, gB, gStride);
    gA += 64; gB += 64;
    issue_tile(sbase + GSTAGE_BYTES + sOffA, sbase + GSTAGE_BYTES + sOffB, gA, gB, gStride);
    gA += 64; gB += 64;

    uint32_t wOff = 2 * GSTAGE_BYTES, rOff = 0;

    for (int t = 0; t < ntile; ++t) {
        if (t == ntile - 1) { CP_WAIT0(); } else { CP_WAIT1(); }
        __syncthreads();
        // NOTE: single barrier per tile. The barrier above (after the cp.async
        // wait) orders all warps' iteration t-1 smem reads (LDSM completion is
        // forced by the register deps of their issued MMAs) before this
        // iteration's cp.async writes into slot (t+2)%3 == (t-1)%3.
        if (t + 2 < ntile) {
            issue_tile(sbase + wOff + sOffA, sbase + wOff + sOffB, gA, gB, gStride);
            gA += 64; gB += 64;
            wOff = (wOff == 2 * GSTAGE_BYTES) ? 0u : wOff + GSTAGE_BYTES;
        }

        #pragma unroll
        for (int j = 0; j < 4; ++j) {
            uint32_t a[4][4], b[2][4];
            #pragma unroll
            for (int mt = 0; mt < 4; ++mt)
                LDSM4(a[mt][0], a[mt][1], a[mt][2], a[mt][3],
                      aAddr[mt] + rOff + (((uint32_t)(j * 32) + hiA) ^ aSw[mt]));
            #pragma unroll
            for (int ng = 0; ng < 2; ++ng)
                LDSM4(b[ng][0], b[ng][1], b[ng][2], b[ng][3],
                      bAddr[ng] + rOff + (((uint32_t)(j * 32) + hiB) ^ bSw[ng]));
            #pragma unroll
            for (int mt = 0; mt < 4; ++mt)
                #pragma unroll
                for (int nt = 0; nt < 4; ++nt) {
                    const int ng = nt >> 1;
                    if (nt & 1) MMA16816F16(acc[mt][nt], a[mt][0], a[mt][1], a[mt][2], a[mt][3],
                                            b[ng][2], b[ng][3]);
                    else        MMA16816F16(acc[mt][nt], a[mt][0], a[mt][1], a[mt][2], a[mt][3],
                                            b[ng][0], b[ng][1]);
                }
        }
        rOff = (rOff == 2 * GSTAGE_BYTES) ? 0u : rOff + GSTAGE_BYTES;
    }
}

// ---- fused up-projection: [h | t0 | t1] = gelu(x_norm @ [W1|a1|b1] + bias'), fp16 out ----
__global__ void __launch_bounds__(256, 2) gemm_up(
    const __half* __restrict__ A, const __half* __restrict__ B,
    const float* __restrict__ bias,
    __half* __restrict__ Hh, __half* __restrict__ T0, __half* __restrict__ T1)
{
    float acc[4][4][4];
    const int bm = blockIdx.y, bn = blockIdx.x;
    gemm_mainloop(A, B, HID, bm, bn, acc);

    __half* outH; int No; int colL;
    if (bn < 32)      { outH = Hh; No = 4096; colL = bn * 128; }
    else if (bn < 34) { outH = T0; No = 256;  colL = (bn - 32) * 128; }
    else              { outH = T1; No = 512;  colL = (bn - 34) * 128; }

    const int lane = threadIdx.x & 31, wid = threadIdx.x >> 5;
    const int warp_m = wid & 1, warp_n = wid >> 1;
    const int row0 = bm * 128 + warp_m * 64 + (lane >> 2);
    const int cw   = warp_n * 32 + (lane & 3) * 2;

    #pragma unroll
    for (int mt = 0; mt < 4; ++mt) {
        #pragma unroll
        for (int nt = 0; nt < 4; ++nt) {
            const int cc = cw + nt * 8;
            const float bz0 = bias[bn * 128 + cc];
            const float bz1 = bias[bn * 128 + cc + 1];
            float v[4];
            v[0] = gelu_exact(acc[mt][nt][0] + bz0);
            v[1] = gelu_exact(acc[mt][nt][1] + bz1);
            v[2] = gelu_exact(acc[mt][nt][2] + bz0);
            v[3] = gelu_exact(acc[mt][nt][3] + bz1);
            const int gc = colL + cc;
            const size_t r0 = (size_t)(row0 + mt * 16);
            const size_t r1 = r0 + 8;
            *reinterpret_cast<__half2*>(outH + r0 * No + gc) =
                __halves2half2(__float2half_rn(v[0]), __float2half_rn(v[1]));
            *reinterpret_cast<__half2*>(outH + r1 * No + gc) =
                __halves2half2(__float2half_rn(v[2]), __float2half_rn(v[3]));
        }
    }
}

// ---- fused adapter-down: ad = t @ a2^T + bias, fp32 out ----
__global__ void __launch_bounds__(256, 2) gemm_down(
    const __half* __restrict__ A0, const __half* __restrict__ B0,
    const float* __restrict__ bias0, float* __restrict__ C0,
    const __half* __restrict__ A1, const __half* __restrict__ B1,
    const float* __restrict__ bias1, float* __restrict__ C1)
{
    float acc[4][4][4];
    const int bm = blockIdx.y, bn = blockIdx.x;
    const __half* A; const __half* B; const float* bias; float* C; int K;
    if (blockIdx.z == 0) { A = A0; B = B0; bias = bias0; C = C0; K = 256; }
    else                 { A = A1; B = B1; bias = bias1; C = C1; K = 512; }
    gemm_mainloop(A, B, K, bm, bn, acc);

    const int lane = threadIdx.x & 31, wid = threadIdx.x >> 5;
    const int warp_m = wid & 1, warp_n = wid >> 1;
    const int row0 = bm * 128 + warp_m * 64 + (lane >> 2);
    const int cw   = warp_n * 32 + (lane & 3) * 2;

    #pragma unroll
    for (int mt = 0; mt < 4; ++mt) {
        #pragma unroll
        for (int nt = 0; nt < 4; ++nt) {
            const int cc = cw + nt * 8;
            const int gc = bn * 128 + cc;
            const float bz0 = bias[gc], bz1 = bias[gc + 1];
            const size_t r0 = (size_t)(row0 + mt * 16);
            const size_t r1 = r0 + 8;
            *reinterpret_cast<float2*>(C + r0 * HID + gc) =
                make_float2(acc[mt][nt][0] + bz0, acc[mt][nt][1] + bz1);
            *reinterpret_cast<float2*>(C + r1 * HID + gc) =
                make_float2(acc[mt][nt][2] + bz0, acc[mt][nt][3] + bz1);
        }
    }
}

// ---- final: out = (inv_r*(h@(g∘W2) − mu_r*c1) + c2)*w_r + asel*(1−w_r) ----
__global__ void __launch_bounds__(256, 2) gemm_final(
    const __half* __restrict__ A, const __half* __restrict__ B,
    const float* __restrict__ c1, const float* __restrict__ c2,
    const float* __restrict__ mu, const float* __restrict__ inv,
    const float* __restrict__ wm, const int* __restrict__ idx,
    const float* __restrict__ ad0, const float* __restrict__ ad1,
    const __half* __restrict__ xnh, float* __restrict__ out)
{
    float acc[4][4][4];
    const int bm = blockIdx.y, bn = blockIdx.x;
    gemm_mainloop(A, B, FFN, bm, bn, acc);

    const int lane = threadIdx.x & 31, wid = threadIdx.x >> 5;
    const int warp_m = wid & 1, warp_n = wid >> 1;
    const int row0 = bm * 128 + warp_m * 64 + (lane >> 2);
    const int cw   = warp_n * 32 + (lane & 3) * 2;

    #pragma unroll
    for (int mt = 0; mt < 4; ++mt) {
        #pragma unroll
        for (int rr = 0; rr < 2; ++rr) {
            const int r = row0 + mt * 16 + rr * 8;
            const float muv = mu[r], invv = inv[r];
            const float w = wm[r], w1 = 1.0f - w;
            const int id = idx[r];
            #pragma unroll
            for (int nt = 0; nt < 4; ++nt) {
                const int gc = bn * 128 + cw + nt * 8;
                const float v0 = invv * (acc[mt][nt][rr * 2 + 0] - muv * c1[gc])     + c2[gc];
                const float v1 = invv * (acc[mt][nt][rr * 2 + 1] - muv * c1[gc + 1]) + c2[gc + 1];
                float ax, ay;
                if (id == 2) {
                    const __half2 hv = *reinterpret_cast<const __half2*>(
                        xnh + (size_t)r * HID + gc);
                    const float2 f = __half22float2(hv);
                    ax = f.x; ay = f.y;
                } else {
                    const float* ad = (id == 0) ? ad0 : ad1;
                    const float2 f = *reinterpret_cast<const float2*>(
                        ad + (size_t)r * HID + gc);
                    ax = f.x; ay = f.y;
                }
                *reinterpret_cast<float2*>(out + (size_t)r * HID + gc) =
                    make_float2(v0 * w + ax * w1, v1 * w + ay * w1);
            }
        }
    }
}

// ============================ launch ============================
extern "C" void kernel_launch(void* const* d_in, const int* in_sizes, int n_in,
                              void* d_out, int out_size)
{
    const float* x        = (const float*)d_in[0];
    const float* wm       = (const float*)d_in[1];
    const int*   widx     = (const int*)  d_in[2];
    const float* ln_in_g  = (const float*)d_in[3];
    const float* ln_in_b  = (const float*)d_in[4];
    const float* W1       = (const float*)d_in[5];
    const float* b1       = (const float*)d_in[6];
    const float* ln_h_g   = (const float*)d_in[7];
    const float* ln_h_b   = (const float*)d_in[8];
    const float* W2       = (const float*)d_in[9];
    const float* b2       = (const float*)d_in[10];
    const float* a256_w1  = (const float*)d_in[11];
    const float* a256_b1  = (const float*)d_in[12];
    const float* a256_w2  = (const float*)d_in[13];
    const float* a256_b2  = (const float*)d_in[14];
    const float* a512_w1  = (const float*)d_in[15];
    const float* a512_b1  = (const float*)d_in[16];
    const float* a512_w2  = (const float*)d_in[17];
    const float* a512_b2  = (const float*)d_in[18];
    float* out = (float*)d_out;

    cudaFuncSetAttribute(gemm_up,    cudaFuncAttributeMaxDynamicSharedMemorySize, GEMM_SMEM);
    cudaFuncSetAttribute(gemm_down,  cudaFuncAttributeMaxDynamicSharedMemorySize, GEMM_SMEM);
    cudaFuncSetAttribute(gemm_final, cudaFuncAttributeMaxDynamicSharedMemorySize, GEMM_SMEM);

    float *ad0, *ad1, *bup, *mu, *inv, *c1, *c2, *p1, *p2;
    __half *xnh, *hh, *t0h, *t1h, *wup, *w2t, *a2t, *b2t;
    cudaGetSymbolAddress((void**)&ad0,   g_ad0);
    cudaGetSymbolAddress((void**)&ad1,   g_ad1);
    cudaGetSymbolAddress((void**)&bup,   g_bup);
    cudaGetSymbolAddress((void**)&mu,    g_mu);
    cudaGetSymbolAddress((void**)&inv,   g_inv);
    cudaGetSymbolAddress((void**)&c1,    g_c1);
    cudaGetSymbolAddress((void**)&c2,    g_c2);
    cudaGetSymbolAddress((void**)&p1,    g_p1);
    cudaGetSymbolAddress((void**)&p2,    g_p2);
    cudaGetSymbolAddress((void**)&xnh,   g_xnh);
    cudaGetSymbolAddress((void**)&hh,    g_hh);
    cudaGetSymbolAddress((void**)&t0h,   g_t0h);
    cudaGetSymbolAddress((void**)&t1h,   g_t1h);
    cudaGetSymbolAddress((void**)&wup,   g_wup);
    cudaGetSymbolAddress((void**)&w2t,   g_w2t);
    cudaGetSymbolAddress((void**)&a2t,   g_a2t);
    cudaGetSymbolAddress((void**)&b2t,   g_b2t);

    // weight prep
    transpose_big<<<dim3(128, 128, 2), 256>>>(W1, W2, ln_h_g, wup, w2t);
    transpose_adapters<<<dim3(32, 32, 4), 256>>>(a256_w1, a256_w2, a512_w1, a512_w2,
                                                 wup, a2t, b2t);
    bias_concat<<<(NUP + 255) / 256, 256>>>(b1, a256_b1, a512_b1, bup);
    colsum_partial<<<dim3(HID / 128, 64), 128>>>(W2, ln_h_g, ln_h_b, p1, p2);
    colsum_reduce<<<HID / 256, 256>>>(p1, p2, b2, c1, c2);

    // x_norm (fp16 only)
    ln1024_kernel<<<TOKENS, 256>>>(x, ln_in_g, ln_in_b, xnh);

    // fused up-projection (h, t0, t1 all fp16)
    gemm_up<<<dim3(NUP / 128, TOKENS / 128), 256, GEMM_SMEM>>>(
        xnh, wup, bup, hh, t0h, t1h);

    // row stats of h (replaces LN pass)
    rowstat_kernel<<<TOKENS, 256>>>(hh, mu, inv);

    // adapter-down projections
    gemm_down<<<dim3(HID / 128, TOKENS / 128, 2), 256, GEMM_SMEM>>>(
        t0h, a2t, a256_b2, ad0, t1h, b2t, a512_b2, ad1);

    // final GEMM with LN-correction + routed combine fused in epilogue
    gemm_final<<<dim3(HID / 128, TOKENS / 128), 256, GEMM_SMEM>>>(
        hh, w2t, c1, c2, mu, inv, wm, widx, ad0, ad1, xnh, out);
}

// round 9
// speedup vs baseline: 8.3027x; 1.0410x over previous
#include <cuda_runtime.h>
#include <cuda_fp16.h>
#include <math.h>
#include <stdint.h>

#define TOKENS 8192
#define HID    1024
#define FFN    4096
#define NUP    4864      // 4096 + 256 + 512 fused up-projection width

// ============================ scratch (device globals) ============================
__device__ __half g_xnh[TOKENS * HID];         // permuted row space
__device__ __half g_hh[TOKENS * FFN];          // permuted
__device__ float  g_mu[TOKENS], g_inv[TOKENS]; // permuted
__device__ float  g_ad0[TOKENS * HID], g_ad1[TOKENS * HID];   // permuted
__device__ __half g_t0h[TOKENS * 256];         // permuted
__device__ __half g_t1h[TOKENS * 512];         // permuted
__device__ __half g_wup[NUP * HID];
__device__ float  g_bup[NUP];
__device__ __half g_w2t[HID * FFN];            // (ln_h_g ∘ W2)^T fp16
__device__ __half g_a2t[HID * 256];
__device__ __half g_b2t[HID * 512];
__device__ float  g_c1[HID], g_c2[HID];
__device__ float  g_p1[64 * HID], g_p2[64 * HID];
__device__ int    g_perm[TOKENS];              // new(p) -> old(o)
__device__ int    g_pos[TOKENS];               // old(o) -> new(p)
__device__ int    g_counts[2];                 // c0, c0+c1

__device__ __forceinline__ float gelu_exact(float x) {
    return 0.5f * x * (1.0f + erff(x * 0.7071067811865475f));
}
__device__ __forceinline__ uint32_t smem_u32(const void* p) {
    uint32_t a;
    asm("{ .reg .u64 t; cvta.to.shared.u64 t, %1; cvt.u32.u64 %0, t; }" : "=r"(a) : "l"(p));
    return a;
}

#define CP_ASYNC16(s, g) \
    asm volatile("cp.async.cg.shared.global [%0], [%1], 16;" :: "r"(s), "l"(g))
#define CP_COMMIT() asm volatile("cp.async.commit_group;")
#define CP_WAIT1()  asm volatile("cp.async.wait_group 1;")
#define CP_WAIT0()  asm volatile("cp.async.wait_group 0;")

#define LDSM4(r0, r1, r2, r3, addr) \
    asm volatile("ldmatrix.sync.aligned.m8n8.x4.shared.b16 {%0,%1,%2,%3}, [%4];" \
                 : "=r"(r0), "=r"(r1), "=r"(r2), "=r"(r3) : "r"(addr))

#define MMA16816F16(d, a0, a1, a2, a3, b0, b1) \
    asm volatile("mma.sync.aligned.m16n8k16.row.col.f32.f16.f16.f32 " \
                 "{%0,%1,%2,%3}, {%4,%5,%6,%7}, {%8,%9}, {%0,%1,%2,%3};" \
                 : "+f"((d)[0]), "+f"((d)[1]), "+f"((d)[2]), "+f"((d)[3]) \
                 : "r"(a0), "r"(a1), "r"(a2), "r"(a3), "r"(b0), "r"(b1))

// ============================ weight prep ============================
__device__ __forceinline__ void do_transpose(
    const float* __restrict__ W, int K, int N, __half* __restrict__ T, int rowOff,
    const float* __restrict__ scale)
{
    __shared__ float s[32][33];
    const int n0 = blockIdx.x * 32, k0 = blockIdx.y * 32;
    if (n0 >= N || k0 >= K) return;
    const int tr = threadIdx.x >> 3;
    const int tc = (threadIdx.x & 7) * 4;
    const float4 v = *reinterpret_cast<const float4*>(W + (size_t)(k0 + tr) * N + n0 + tc);
    s[tr][tc + 0] = v.x; s[tr][tc + 1] = v.y; s[tr][tc + 2] = v.z; s[tr][tc + 3] = v.w;
    __syncthreads();
    const size_t off = (size_t)(rowOff + n0 + tr) * K + k0 + tc;
    #pragma unroll
    for (int q = 0; q < 2; ++q) {
        float x0 = s[tc + q * 2 + 0][tr];
        float x1 = s[tc + q * 2 + 1][tr];
        if (scale) {
            x0 *= scale[k0 + tc + q * 2 + 0];
            x1 *= scale[k0 + tc + q * 2 + 1];
        }
        *reinterpret_cast<__half2*>(T + off + q * 2) =
            __halves2half2(__float2half_rn(x0), __float2half_rn(x1));
    }
}

__global__ void __launch_bounds__(256) transpose_big(
    const float* __restrict__ W1, const float* __restrict__ W2,
    const float* __restrict__ lnhg, __half* wup, __half* w2t)
{
    if (blockIdx.z == 0) do_transpose(W1, HID, FFN, wup, 0, nullptr);
    else                 do_transpose(W2, FFN, HID, w2t, 0, lnhg);
}

// stable counting sort of 8192 idx values into perm/pos, 256 threads x 32 elems
__device__ void do_build_perm(const int* __restrict__ idx, int* __restrict__ perm,
                              int* __restrict__ pos, int* __restrict__ counts)
{
    __shared__ int cnt[3][256];
    const int t = threadIdx.x;
    int l0 = 0, l1 = 0, l2 = 0;
    for (int i = 0; i < 32; ++i) {
        const int v = idx[t * 32 + i];
        l0 += (v == 0); l1 += (v == 1); l2 += (v == 2);
    }
    cnt[0][t] = l0; cnt[1][t] = l1; cnt[2][t] = l2;
    __syncthreads();
    for (int off = 1; off < 256; off <<= 1) {
        const int v0 = (t >= off) ? cnt[0][t - off] : 0;
        const int v1 = (t >= off) ? cnt[1][t - off] : 0;
        const int v2 = (t >= off) ? cnt[2][t - off] : 0;
        __syncthreads();
        cnt[0][t] += v0; cnt[1][t] += v1; cnt[2][t] += v2;
        __syncthreads();
    }
    const int tot0 = cnt[0][255], tot1 = cnt[1][255];
    int b0 = cnt[0][t] - l0;
    int b1 = tot0 + cnt[1][t] - l1;
    int b2 = tot0 + tot1 + cnt[2][t] - l2;
    for (int i = 0; i < 32; ++i) {
        const int o = t * 32 + i;
        const int v = idx[o];
        const int p = (v == 0) ? b0++ : ((v == 1) ? b1++ : b2++);
        perm[p] = o;
        pos[o]  = p;
    }
    if (t == 0) { counts[0] = tot0; counts[1] = tot0 + tot1; }
}

__global__ void __launch_bounds__(256) prep_small(
    const float* __restrict__ aw1, const float* __restrict__ aw2,
    const float* __restrict__ bw1, const float* __restrict__ bw2,
    __half* wup, __half* a2t, __half* b2t,
    const float* __restrict__ b1, const float* __restrict__ ab1,
    const float* __restrict__ bb1, float* __restrict__ bup,
    const int* __restrict__ widx, int* perm, int* pos, int* counts)
{
    switch (blockIdx.z) {
        case 0: do_transpose(aw1, HID, 256, wup, 4096, nullptr); break;
        case 1: do_transpose(aw2, 256, HID, a2t, 0, nullptr);    break;
        case 2: do_transpose(bw1, HID, 512, wup, 4352, nullptr); break;
        case 3: do_transpose(bw2, 512, HID, b2t, 0, nullptr);    break;
        case 4: {
            const int i = (blockIdx.y * 32 + blockIdx.x) * 256 + threadIdx.x;
            if (i < NUP) {
                float v;
                if (i < 4096) v = b1[i];
                else if (i < 4352) v = ab1[i - 4096];
                else v = bb1[i - 4352];
                bup[i] = v;
            }
            break;
        }
        default:
            if (blockIdx.x == 0 && blockIdx.y == 0)
                do_build_perm(widx, perm, pos, counts);
            break;
    }
}

// c1[n] = sum_f g[f]*W2[f,n];  c2[n] = sum_f b[f]*W2[f,n] + b2[n]
__global__ void __launch_bounds__(128) colsum_partial(
    const float* __restrict__ W2, const float* __restrict__ g,
    const float* __restrict__ b, float* __restrict__ p1, float* __restrict__ p2)
{
    const int n = blockIdx.x * 128 + threadIdx.x;
    const int f0 = blockIdx.y * 64;
    float s1 = 0.0f, s2 = 0.0f;
    #pragma unroll 8
    for (int f = f0; f < f0 + 64; ++f) {
        const float w = W2[(size_t)f * HID + n];
        s1 += g[f] * w;
        s2 += b[f] * w;
    }
    p1[blockIdx.y * HID + n] = s1;
    p2[blockIdx.y * HID + n] = s2;
}

__global__ void __launch_bounds__(256) colsum_reduce(
    const float* __restrict__ p1, const float* __restrict__ p2,
    const float* __restrict__ b2, float* __restrict__ c1, float* __restrict__ c2)
{
    const int n = blockIdx.x * 256 + threadIdx.x;
    float s1 = 0.0f, s2 = 0.0f;
    #pragma unroll
    for (int q = 0; q < 64; ++q) { s1 += p1[q * HID + n]; s2 += p2[q * HID + n]; }
    c1[n] = s1;
    c2[n] = s2 + b2[n];
}

// ============================ reductions / LN ============================
__device__ __forceinline__ void block_reduce_sum2(float& s, float& ss) {
    #pragma unroll
    for (int off = 16; off > 0; off >>= 1) {
        s  += __shfl_down_sync(0xffffffffu, s, off);
        ss += __shfl_down_sync(0xffffffffu, ss, off);
    }
    __shared__ float sh_s[8], sh_ss[8];
    int warp = threadIdx.x >> 5, lane = threadIdx.x & 31;
    if (lane == 0) { sh_s[warp] = s; sh_ss[warp] = ss; }
    __syncthreads();
    if (warp == 0) {
        s  = (lane < 8) ? sh_s[lane]  : 0.0f;
        ss = (lane < 8) ? sh_ss[lane] : 0.0f;
        #pragma unroll
        for (int off = 4; off > 0; off >>= 1) {
            s  += __shfl_down_sync(0xffffffffu, s, off);
            ss += __shfl_down_sync(0xffffffffu, ss, off);
        }
        if (lane == 0) { sh_s[0] = s; sh_ss[0] = ss; }
    }
    __syncthreads();
    s = sh_s[0]; ss = sh_ss[0];
}

// LN(x) row r -> fp16 at permuted row pos[r]
__global__ void __launch_bounds__(256) ln1024_kernel(
    const float* __restrict__ in, const float* __restrict__ gw,
    const float* __restrict__ bw, const int* __restrict__ pos,
    __half* __restrict__ oh)
{
    const int row = blockIdx.x;
    const float4* inr = reinterpret_cast<const float4*>(in) + (size_t)row * 256;
    const float4 v = inr[threadIdx.x];
    float s  = v.x + v.y + v.z + v.w;
    float ss = v.x * v.x + v.y * v.y + v.z * v.z + v.w * v.w;
    block_reduce_sum2(s, ss);
    const float mu  = s * (1.0f / HID);
    const float var = ss * (1.0f / HID) - mu * mu;
    const float inv = rsqrtf(var + 1e-5f);

    const int c = threadIdx.x;
    const float4 gv = reinterpret_cast<const float4*>(gw)[c];
    const float4 bv = reinterpret_cast<const float4*>(bw)[c];
    float4 o;
    o.x = (v.x - mu) * inv * gv.x + bv.x;
    o.y = (v.y - mu) * inv * gv.y + bv.y;
    o.z = (v.z - mu) * inv * gv.z + bv.z;
    o.w = (v.w - mu) * inv * gv.w + bv.w;
    __half2* ohr = reinterpret_cast<__half2*>(oh) + (size_t)pos[row] * 512;
    ohr[c * 2 + 0] = __halves2half2(__float2half_rn(o.x), __float2half_rn(o.y));
    ohr[c * 2 + 1] = __halves2half2(__float2half_rn(o.z), __float2half_rn(o.w));
}

// per-row mean/inv-std of h (fp16, width 4096), permuted space
__global__ void __launch_bounds__(256) rowstat_kernel(
    const __half* __restrict__ hh, float* __restrict__ mu, float* __restrict__ inv)
{
    const size_t row = blockIdx.x;
    const __half2* hr = reinterpret_cast<const __half2*>(hh) + row * (FFN / 2);
    float s = 0.0f, ss = 0.0f;
    #pragma unroll
    for (int i = 0; i < 8; ++i) {
        const float2 f = __half22float2(hr[threadIdx.x + i * 256]);
        s  += f.x + f.y;
        ss += f.x * f.x + f.y * f.y;
    }
    block_reduce_sum2(s, ss);
    if (threadIdx.x == 0) {
        const float m = s * (1.0f / FFN);
        mu[row]  = m;
        inv[row] = rsqrtf(ss * (1.0f / FFN) - m * m + 1e-5f);
    }
}

// ============================ fp16 mma.sync GEMM mainloop ============================
#define GSTAGES 3
#define GSTAGE_BYTES 32768
#define GEMM_SMEM (GSTAGES * GSTAGE_BYTES)

__device__ __forceinline__ void issue_tile(
    uint32_t dstA, uint32_t dstB,
    const __half* gA, const __half* gB, size_t gStride)
{
    #pragma unroll
    for (int p = 0; p < 4; ++p)
        CP_ASYNC16(dstA + p * 4096, gA + p * gStride);
    #pragma unroll
    for (int p = 0; p < 4; ++p)
        CP_ASYNC16(dstB + p * 4096, gB + p * gStride);
    CP_COMMIT();
}

__device__ __forceinline__ void gemm_mainloop(
    const __half* __restrict__ A, const __half* __restrict__ B,
    int K, int bm, int bn, float (&acc)[4][4][4])
{
    extern __shared__ char smem[];
    const uint32_t sbase = smem_u32(smem);
    const int tid = threadIdx.x, lane = tid & 31, wid = tid >> 5;
    const int warp_m = wid & 1, warp_n = wid >> 1;

    const int lrow = tid >> 3;
    const int lch  = tid & 7;
    const uint32_t sOffA = (uint32_t)lrow * 128 + ((lch ^ (lrow & 7)) << 4);
    const uint32_t sOffB = sOffA + 16384;
    const __half* gA = A + (size_t)(bm * 128 + lrow) * K + lch * 8;
    const __half* gB = B + (size_t)(bn * 128 + lrow) * K + lch * 8;
    const size_t gStride = (size_t)32 * K;

    uint32_t aAddr[4], bAddr[2], aSw[4], bSw[2];
    const uint32_t hiA = (lane & 16);
    const uint32_t hiB = ((lane & 8) << 1);
    #pragma unroll
    for (int mt = 0; mt < 4; ++mt) {
        const int r = warp_m * 64 + mt * 16 + (lane & 15);
        aAddr[mt] = sbase + r * 128;
        aSw[mt]   = ((r & 7) << 4);
    }
    #pragma unroll
    for (int ng = 0; ng < 2; ++ng) {
        const int r = warp_n * 32 + ng * 16 + (lane & 7) + ((lane & 16) >> 1);
        bAddr[ng] = sbase + 16384 + r * 128;
        bSw[ng]   = ((r & 7) << 4);
    }

    #pragma unroll
    for (int i = 0; i < 4; ++i)
        #pragma unroll
        for (int j = 0; j < 4; ++j)
            #pragma unroll
            for (int q = 0; q < 4; ++q) acc[i][j][q] = 0.0f;

    const int ntile = K >> 6;

    issue_tile(sbase + sOffA, sbase + sOffB, gA, gB, gStride);
    gA += 64; gB += 64;
    issue_tile(sbase + GSTAGE_BYTES + sOffA, sbase + GSTAGE_BYTES + sOffB, gA, gB, gStride);
    gA += 64; gB += 64;

    uint32_t wOff = 2 * GSTAGE_BYTES, rOff = 0;

    for (int t = 0; t < ntile; ++t) {
        if (t == ntile - 1) { CP_WAIT0(); } else { CP_WAIT1(); }
        __syncthreads();
        if (t + 2 < ntile) {
            issue_tile(sbase + wOff + sOffA, sbase + wOff + sOffB, gA, gB, gStride);
            gA += 64; gB += 64;
            wOff = (wOff == 2 * GSTAGE_BYTES) ? 0u : wOff + GSTAGE_BYTES;
        }

        #pragma unroll
        for (int j = 0; j < 4; ++j) {
            uint32_t a[4][4], b[2][4];
            #pragma unroll
            for (int mt = 0; mt < 4; ++mt)
                LDSM4(a[mt][0], a[mt][1], a[mt][2], a[mt][3],
                      aAddr[mt] + rOff + (((uint32_t)(j * 32) + hiA) ^ aSw[mt]));
            #pragma unroll
            for (int ng = 0; ng < 2; ++ng)
                LDSM4(b[ng][0], b[ng][1], b[ng][2], b[ng][3],
                      bAddr[ng] + rOff + (((uint32_t)(j * 32) + hiB) ^ bSw[ng]));
            #pragma unroll
            for (int mt = 0; mt < 4; ++mt)
                #pragma unroll
                for (int nt = 0; nt < 4; ++nt) {
                    const int ng = nt >> 1;
                    if (nt & 1) MMA16816F16(acc[mt][nt], a[mt][0], a[mt][1], a[mt][2], a[mt][3],
                                            b[ng][2], b[ng][3]);
                    else        MMA16816F16(acc[mt][nt], a[mt][0], a[mt][1], a[mt][2], a[mt][3],
                                            b[ng][0], b[ng][1]);
                }
        }
        rOff = (rOff == 2 * GSTAGE_BYTES) ? 0u : rOff + GSTAGE_BYTES;
    }
}

// ---- fused up-projection with routed early-exit on adapter column tiles ----
__global__ void __launch_bounds__(256, 2) gemm_up(
    const __half* __restrict__ A, const __half* __restrict__ B,
    const float* __restrict__ bias, const int* __restrict__ counts,
    __half* __restrict__ Hh, __half* __restrict__ T0, __half* __restrict__ T1)
{
    const int bm = blockIdx.y, bn = blockIdx.x;
    if (bn >= 32) {
        if (bn < 34) {                         // t0 columns: rows [0, c0)
            if (bm * 128 >= counts[0]) return;
        } else {                               // t1 columns: rows [c0, c01)
            if (bm * 128 >= counts[1] || bm * 128 + 128 <= counts[0]) return;
        }
    }
    float acc[4][4][4];
    gemm_mainloop(A, B, HID, bm, bn, acc);

    __half* outH; int No; int colL;
    if (bn < 32)      { outH = Hh; No = 4096; colL = bn * 128; }
    else if (bn < 34) { outH = T0; No = 256;  colL = (bn - 32) * 128; }
    else              { outH = T1; No = 512;  colL = (bn - 34) * 128; }

    const int lane = threadIdx.x & 31, wid = threadIdx.x >> 5;
    const int warp_m = wid & 1, warp_n = wid >> 1;
    const int row0 = bm * 128 + warp_m * 64 + (lane >> 2);
    const int cw   = warp_n * 32 + (lane & 3) * 2;

    #pragma unroll
    for (int mt = 0; mt < 4; ++mt) {
        #pragma unroll
        for (int nt = 0; nt < 4; ++nt) {
            const int cc = cw + nt * 8;
            const float bz0 = bias[bn * 128 + cc];
            const float bz1 = bias[bn * 128 + cc + 1];
            float v[4];
            v[0] = gelu_exact(acc[mt][nt][0] + bz0);
            v[1] = gelu_exact(acc[mt][nt][1] + bz1);
            v[2] = gelu_exact(acc[mt][nt][2] + bz0);
            v[3] = gelu_exact(acc[mt][nt][3] + bz1);
            const int gc = colL + cc;
            const size_t r0 = (size_t)(row0 + mt * 16);
            const size_t r1 = r0 + 8;
            *reinterpret_cast<__half2*>(outH + r0 * No + gc) =
                __halves2half2(__float2half_rn(v[0]), __float2half_rn(v[1]));
            *reinterpret_cast<__half2*>(outH + r1 * No + gc) =
                __halves2half2(__float2half_rn(v[2]), __float2half_rn(v[3]));
        }
    }
}

// ---- adapter-down with routed early-exit ----
__global__ void __launch_bounds__(256, 2) gemm_down(
    const __half* __restrict__ A0, const __half* __restrict__ B0,
    const float* __restrict__ bias0, float* __restrict__ C0,
    const __half* __restrict__ A1, const __half* __restrict__ B1,
    const float* __restrict__ bias1, float* __restrict__ C1,
    const int* __restrict__ counts)
{
    const int bm = blockIdx.y, bn = blockIdx.x;
    const __half* A; const __half* B; const float* bias; float* C; int K;
    if (blockIdx.z == 0) {
        if (bm * 128 >= counts[0]) return;
        A = A0; B = B0; bias = bias0; C = C0; K = 256;
    } else {
        if (bm * 128 >= counts[1] || bm * 128 + 128 <= counts[0]) return;
        A = A1; B = B1; bias = bias1; C = C1; K = 512;
    }
    float acc[4][4][4];
    gemm_mainloop(A, B, K, bm, bn, acc);

    const int lane = threadIdx.x & 31, wid = threadIdx.x >> 5;
    const int warp_m = wid & 1, warp_n = wid >> 1;
    const int row0 = bm * 128 + warp_m * 64 + (lane >> 2);
    const int cw   = warp_n * 32 + (lane & 3) * 2;

    #pragma unroll
    for (int mt = 0; mt < 4; ++mt) {
        #pragma unroll
        for (int nt = 0; nt < 4; ++nt) {
            const int cc = cw + nt * 8;
            const int gc = bn * 128 + cc;
            const float bz0 = bias[gc], bz1 = bias[gc + 1];
            const size_t r0 = (size_t)(row0 + mt * 16);
            const size_t r1 = r0 + 8;
            *reinterpret_cast<float2*>(C + r0 * HID + gc) =
                make_float2(acc[mt][nt][0] + bz0, acc[mt][nt][1] + bz1);
            *reinterpret_cast<float2*>(C + r1 * HID + gc) =
                make_float2(acc[mt][nt][2] + bz0, acc[mt][nt][3] + bz1);
        }
    }
}

// ---- final GEMM: LN-correction + routed combine + un-permute on store ----
__global__ void __launch_bounds__(256, 2) gemm_final(
    const __half* __restrict__ A, const __half* __restrict__ B,
    const float* __restrict__ c1, const float* __restrict__ c2,
    const float* __restrict__ mu, const float* __restrict__ inv,
    const float* __restrict__ wm, const int* __restrict__ perm,
    const int* __restrict__ counts,
    const float* __restrict__ ad0, const float* __restrict__ ad1,
    const __half* __restrict__ xnh, float* __restrict__ out)
{
    float acc[4][4][4];
    const int bm = blockIdx.y, bn = blockIdx.x;
    gemm_mainloop(A, B, FFN, bm, bn, acc);

    const int lane = threadIdx.x & 31, wid = threadIdx.x >> 5;
    const int warp_m = wid & 1, warp_n = wid >> 1;
    const int row0 = bm * 128 + warp_m * 64 + (lane >> 2);
    const int cw   = warp_n * 32 + (lane & 3) * 2;
    const int c0 = counts[0], c01 = counts[1];

    #pragma unroll
    for (int mt = 0; mt < 4; ++mt) {
        #pragma unroll
        for (int rr = 0; rr < 2; ++rr) {
            const int p = row0 + mt * 16 + rr * 8;      // permuted row
            const int o = perm[p];                       // original row
            const float muv = mu[p], invv = inv[p];
            const float w = wm[o], w1 = 1.0f - w;
            const int id = (p < c0) ? 0 : ((p < c01) ? 1 : 2);
            #pragma unroll
            for (int nt = 0; nt < 4; ++nt) {
                const int gc = bn * 128 + cw + nt * 8;
                const float v0 = invv * (acc[mt][nt][rr * 2 + 0] - muv * c1[gc])     + c2[gc];
                const float v1 = invv * (acc[mt][nt][rr * 2 + 1] - muv * c1[gc + 1]) + c2[gc + 1];
                float ax, ay;
                if (id == 2) {
                    const float2 f = __half22float2(
                        *reinterpret_cast<const __half2*>(xnh + (size_t)p * HID + gc));
                    ax = f.x; ay = f.y;
                } else {
                    const float* ad = (id == 0) ? ad0 : ad1;
                    const float2 f = *reinterpret_cast<const float2*>(
                        ad + (size_t)p * HID + gc);
                    ax = f.x; ay = f.y;
                }
                *reinterpret_cast<float2*>(out + (size_t)o * HID + gc) =
                    make_float2(v0 * w + ax * w1, v1 * w + ay * w1);
            }
        }
    }
}

// ============================ launch ============================
extern "C" void kernel_launch(void* const* d_in, const int* in_sizes, int n_in,
                              void* d_out, int out_size)
{
    const float* x        = (const float*)d_in[0];
    const float* wm       = (const float*)d_in[1];
    const int*   widx     = (const int*)  d_in[2];
    const float* ln_in_g  = (const float*)d_in[3];
    const float* ln_in_b  = (const float*)d_in[4];
    const float* W1       = (const float*)d_in[5];
    const float* b1       = (const float*)d_in[6];
    const float* ln_h_g   = (const float*)d_in[7];
    const float* ln_h_b   = (const float*)d_in[8];
    const float* W2       = (const float*)d_in[9];
    const float* b2       = (const float*)d_in[10];
    const float* a256_w1  = (const float*)d_in[11];
    const float* a256_b1  = (const float*)d_in[12];
    const float* a256_w2  = (const float*)d_in[13];
    const float* a256_b2  = (const float*)d_in[14];
    const float* a512_w1  = (const float*)d_in[15];
    const float* a512_b1  = (const float*)d_in[16];
    const float* a512_w2  = (const float*)d_in[17];
    const float* a512_b2  = (const float*)d_in[18];
    float* out = (float*)d_out;

    cudaFuncSetAttribute(gemm_up,    cudaFuncAttributeMaxDynamicSharedMemorySize, GEMM_SMEM);
    cudaFuncSetAttribute(gemm_down,  cudaFuncAttributeMaxDynamicSharedMemorySize, GEMM_SMEM);
    cudaFuncSetAttribute(gemm_final, cudaFuncAttributeMaxDynamicSharedMemorySize, GEMM_SMEM);

    float *ad0, *ad1, *bup, *mu, *inv, *c1, *c2, *p1, *p2;
    __half *xnh, *hh, *t0h, *t1h, *wup, *w2t, *a2t, *b2t;
    int *perm, *pos, *counts;
    cudaGetSymbolAddress((void**)&ad0,   g_ad0);
    cudaGetSymbolAddress((void**)&ad1,   g_ad1);
    cudaGetSymbolAddress((void**)&bup,   g_bup);
    cudaGetSymbolAddress((void**)&mu,    g_mu);
    cudaGetSymbolAddress((void**)&inv,   g_inv);
    cudaGetSymbolAddress((void**)&c1,    g_c1);
    cudaGetSymbolAddress((void**)&c2,    g_c2);
    cudaGetSymbolAddress((void**)&p1,    g_p1);
    cudaGetSymbolAddress((void**)&p2,    g_p2);
    cudaGetSymbolAddress((void**)&xnh,   g_xnh);
    cudaGetSymbolAddress((void**)&hh,    g_hh);
    cudaGetSymbolAddress((void**)&t0h,   g_t0h);
    cudaGetSymbolAddress((void**)&t1h,   g_t1h);
    cudaGetSymbolAddress((void**)&wup,   g_wup);
    cudaGetSymbolAddress((void**)&w2t,   g_w2t);
    cudaGetSymbolAddress((void**)&a2t,   g_a2t);
    cudaGetSymbolAddress((void**)&b2t,   g_b2t);
    cudaGetSymbolAddress((void**)&perm,  g_perm);
    cudaGetSymbolAddress((void**)&pos,   g_pos);
    cudaGetSymbolAddress((void**)&counts, g_counts);

    // [0] big weight transposes
    transpose_big<<<dim3(128, 128, 2), 256>>>(W1, W2, ln_h_g, wup, w2t);
    // [1] small transposes + bias concat + token permutation
    prep_small<<<dim3(32, 32, 6), 256>>>(a256_w1, a256_w2, a512_w1, a512_w2,
                                         wup, a2t, b2t,
                                         b1, a256_b1, a512_b1, bup,
                                         widx, perm, pos, counts);
    // [2] LN(x) -> permuted fp16
    ln1024_kernel<<<TOKENS, 256>>>(x, ln_in_g, ln_in_b, pos, xnh);
    // [3] fused up-projection (profiled slot)
    gemm_up<<<dim3(NUP / 128, TOKENS / 128), 256, GEMM_SMEM>>>(
        xnh, wup, bup, counts, hh, t0h, t1h);
    // [4] row stats of h
    rowstat_kernel<<<TOKENS, 256>>>(hh, mu, inv);
    // [5][6] LN-through-GEMM correction vectors
    colsum_partial<<<dim3(HID / 128, 64), 128>>>(W2, ln_h_g, ln_h_b, p1, p2);
    colsum_reduce<<<HID / 256, 256>>>(p1, p2, b2, c1, c2);
    // [7] adapter-down (routed)
    gemm_down<<<dim3(HID / 128, TOKENS / 128, 2), 256, GEMM_SMEM>>>(
        t0h, a2t, a256_b2, ad0, t1h, b2t, a512_b2, ad1, counts);
    // [8] final GEMM + LN correction + routed combine + un-permute
    gemm_final<<<dim3(HID / 128, TOKENS / 128), 256, GEMM_SMEM>>>(
        hh, w2t, c1, c2, mu, inv, wm, perm, counts, ad0, ad1, xnh, out);
}